// round 1
// baseline (speedup 1.0000x reference)
#include <cuda_runtime.h>
#include <cuda_bf16.h>
#include <math.h>

// Problem constants
#define BB 2
#define SS 2048
#define HH 2048
#define NH 16
#define NKV 4
#define HD 128
#define NE 8
#define II 4096
#define TT (BB*SS)          // 4096 tokens
#define QD (NH*HD)          // 2048
#define KVD (NKV*HD)        // 512
#define NSLOTS (TT*2)       // 8192 expert assignments

// ---------------- static scratch (device globals; no runtime alloc allowed) ----
__device__ float g_x[(size_t)TT*HH];            // 32MB  (x_norm, reused for x2_norm)
__device__ float g_q[(size_t)TT*QD];            // 32MB
__device__ float g_k[(size_t)TT*KVD];           // 8MB
__device__ float g_v[(size_t)TT*KVD];           // 8MB
__device__ float g_scores[(size_t)BB*NH*SS*SS]; // 512MB
__device__ float g_attn[(size_t)TT*QD];         // 32MB
__device__ float g_hid2[(size_t)TT*HH];         // 32MB
__device__ float g_act[(size_t)NSLOTS*II];      // 128MB
__device__ float g_y[(size_t)NSLOTS*HH];        // 64MB
__device__ int   g_topi[NSLOTS];
__device__ float g_topw[NSLOTS];
__device__ int   g_counts[NE];
__device__ int   g_offsets[NE];
__device__ int   g_cursor[NE];
__device__ int   g_tok[NSLOTS];   // token id per sorted slot
__device__ int   g_slot[NSLOTS];  // slot per (token, choice)

// ---------------- small kernels ------------------------------------------------
__global__ void zero_counts_kernel(int* counts) {
    if (threadIdx.x < NE) counts[threadIdx.x] = 0;
}

__global__ void rmsnorm_kernel(const float* __restrict__ in, const float* __restrict__ w,
                               float* __restrict__ out) {
    int t = blockIdx.x;
    const float* row = in + (size_t)t * HH;
    float ss = 0.f;
    for (int h = threadIdx.x; h < HH; h += 256) { float v = row[h]; ss += v * v; }
    __shared__ float red[256];
    red[threadIdx.x] = ss; __syncthreads();
    for (int s = 128; s > 0; s >>= 1) {
        if (threadIdx.x < s) red[threadIdx.x] += red[threadIdx.x + s];
        __syncthreads();
    }
    float scale = rsqrtf(red[0] / (float)HH + 1e-5f);
    for (int h = threadIdx.x; h < HH; h += 256)
        out[(size_t)t * HH + h] = row[h] * scale * w[h];
}

__global__ void rope_kernel(float* __restrict__ q, int nheads, int total) {
    int idx = blockIdx.x * blockDim.x + threadIdx.x;
    if (idx >= total) return;
    int d = idx & 63;
    int rest = idx >> 6;
    int head = rest % nheads;
    int t = rest / nheads;
    int s = t & (SS - 1);
    float inv = __powf(10000.f, -(float)d / 64.f);
    float ang = (float)s * inv;
    float c, si; __sincosf(ang, &si, &c);
    size_t base = (size_t)t * nheads * HD + (size_t)head * HD + d;
    float x1 = q[base], x2 = q[base + 64];
    q[base]      = x1 * c - x2 * si;
    q[base + 64] = x2 * c + x1 * si;
}

// ---------------- generic dense GEMM: C = A(MxK) * B(KxN) [+ D] ---------------
__global__ __launch_bounds__(256) void gemm_nn_kernel(
    const float* __restrict__ A, const float* __restrict__ B,
    const float* __restrict__ D, float* __restrict__ C,
    int M, int N, int K)
{
    __shared__ float As[16][65];
    __shared__ float Bs[16][65];
    int tid = threadIdx.x;
    int tx = tid & 15, ty = tid >> 4;
    int m0 = blockIdx.y * 64, n0 = blockIdx.x * 64;
    float acc[4][4] = {};
    for (int k0 = 0; k0 < K; k0 += 16) {
        for (int l = tid; l < 64 * 16; l += 256) {
            int r = l >> 4, kk = l & 15;
            int gm = m0 + r;
            As[kk][r] = (gm < M) ? A[(size_t)gm * K + k0 + kk] : 0.f;
        }
        for (int l = tid; l < 16 * 64; l += 256) {
            int kk = l >> 6, c = l & 63;
            int gn = n0 + c;
            Bs[kk][c] = (gn < N) ? B[(size_t)(k0 + kk) * N + gn] : 0.f;
        }
        __syncthreads();
        #pragma unroll
        for (int kk = 0; kk < 16; kk++) {
            float a[4], b[4];
            #pragma unroll
            for (int i = 0; i < 4; i++) a[i] = As[kk][ty * 4 + i];
            #pragma unroll
            for (int j = 0; j < 4; j++) b[j] = Bs[kk][tx * 4 + j];
            #pragma unroll
            for (int i = 0; i < 4; i++)
                #pragma unroll
                for (int j = 0; j < 4; j++) acc[i][j] += a[i] * b[j];
        }
        __syncthreads();
    }
    #pragma unroll
    for (int i = 0; i < 4; i++) {
        int gm = m0 + ty * 4 + i;
        if (gm >= M) continue;
        #pragma unroll
        for (int j = 0; j < 4; j++) {
            int gn = n0 + tx * 4 + j;
            if (gn < N) {
                float v = acc[i][j];
                if (D) v += D[(size_t)gm * N + gn];
                C[(size_t)gm * N + gn] = v;
            }
        }
    }
}

// ---------------- attention scores: S[b,h,m,n] = sum_d q*k (NT) ----------------
__global__ __launch_bounds__(256) void gemm_scores_kernel(
    const float* __restrict__ q, const float* __restrict__ k, float* __restrict__ scores)
{
    int z = blockIdx.z; int b = z >> 4, h = z & 15;
    int m0 = blockIdx.y * 64, n0 = blockIdx.x * 64;
    if (n0 > m0 + 63) return;  // causal: fully masked tile
    const float* A  = q + (size_t)b * SS * QD + (size_t)h * HD;
    const float* Bm = k + (size_t)b * SS * KVD + (size_t)(h >> 2) * HD;
    float* C = scores + (size_t)z * SS * SS;
    __shared__ float As[16][65];
    __shared__ float Bs[16][65];
    int tid = threadIdx.x;
    int tx = tid & 15, ty = tid >> 4;
    float acc[4][4] = {};
    for (int k0 = 0; k0 < HD; k0 += 16) {
        for (int l = tid; l < 64 * 16; l += 256) {
            int r = l >> 4, kk = l & 15;
            As[kk][r] = A[(size_t)(m0 + r) * QD + k0 + kk];
        }
        for (int l = tid; l < 64 * 16; l += 256) {
            int c = l >> 4, kk = l & 15;
            Bs[kk][c] = Bm[(size_t)(n0 + c) * KVD + k0 + kk];
        }
        __syncthreads();
        #pragma unroll
        for (int kk = 0; kk < 16; kk++) {
            float a[4], bb[4];
            #pragma unroll
            for (int i = 0; i < 4; i++) a[i] = As[kk][ty * 4 + i];
            #pragma unroll
            for (int j = 0; j < 4; j++) bb[j] = Bs[kk][tx * 4 + j];
            #pragma unroll
            for (int i = 0; i < 4; i++)
                #pragma unroll
                for (int j = 0; j < 4; j++) acc[i][j] += a[i] * bb[j];
        }
        __syncthreads();
    }
    #pragma unroll
    for (int i = 0; i < 4; i++)
        #pragma unroll
        for (int j = 0; j < 4; j++)
            C[(size_t)(m0 + ty * 4 + i) * SS + n0 + tx * 4 + j] = acc[i][j];
}

// ---------------- causal row softmax (with 1/sqrt(HD) scale) -------------------
__global__ void softmax_kernel(float* __restrict__ scores) {
    int z = blockIdx.y, m = blockIdx.x;
    float* row = scores + (size_t)z * SS * SS + (size_t)m * SS;
    int n = m + 1;
    const float scale = 0.08838834764831845f; // 1/sqrt(128)
    __shared__ float red[256];
    float mx = -3.4e38f;
    for (int j = threadIdx.x; j < n; j += 256) mx = fmaxf(mx, row[j]);
    red[threadIdx.x] = mx; __syncthreads();
    for (int s = 128; s > 0; s >>= 1) {
        if (threadIdx.x < s) red[threadIdx.x] = fmaxf(red[threadIdx.x], red[threadIdx.x + s]);
        __syncthreads();
    }
    mx = red[0]; __syncthreads();
    float sum = 0.f;
    for (int j = threadIdx.x; j < n; j += 256) {
        float p = expf((row[j] - mx) * scale);
        row[j] = p;
        sum += p;
    }
    red[threadIdx.x] = sum; __syncthreads();
    for (int s = 128; s > 0; s >>= 1) {
        if (threadIdx.x < s) red[threadIdx.x] += red[threadIdx.x + s];
        __syncthreads();
    }
    float inv = 1.f / red[0];
    for (int j = threadIdx.x; j < n; j += 256) row[j] *= inv;
    // zero up to this row's 64-tile boundary so PV's tile-granular K read is safe
    int bound = ((m >> 6) + 1) << 6;
    for (int j = n + threadIdx.x; j < bound; j += 256) row[j] = 0.f;
}

// ---------------- PV: attn[b,m,h,d] = sum_n P[m,n] * v[n,d] (NN, causal-K) -----
__global__ __launch_bounds__(256) void gemm_pv_kernel(
    const float* __restrict__ P, const float* __restrict__ v, float* __restrict__ attn)
{
    int z = blockIdx.z; int b = z >> 4, h = z & 15;
    int m0 = blockIdx.y * 64, n0 = blockIdx.x * 64;
    const float* A  = P + (size_t)z * SS * SS;
    const float* Bm = v + (size_t)b * SS * KVD + (size_t)(h >> 2) * HD;
    float* C = attn + (size_t)b * SS * QD + (size_t)h * HD;
    int kend = m0 + 64;  // causal: keys beyond this tile are zero
    __shared__ float As[16][65];
    __shared__ float Bs[16][65];
    int tid = threadIdx.x;
    int tx = tid & 15, ty = tid >> 4;
    float acc[4][4] = {};
    for (int k0 = 0; k0 < kend; k0 += 16) {
        for (int l = tid; l < 64 * 16; l += 256) {
            int r = l >> 4, kk = l & 15;
            As[kk][r] = A[(size_t)(m0 + r) * SS + k0 + kk];
        }
        for (int l = tid; l < 16 * 64; l += 256) {
            int kk = l >> 6, c = l & 63;
            Bs[kk][c] = Bm[(size_t)(k0 + kk) * KVD + n0 + c];
        }
        __syncthreads();
        #pragma unroll
        for (int kk = 0; kk < 16; kk++) {
            float a[4], bb[4];
            #pragma unroll
            for (int i = 0; i < 4; i++) a[i] = As[kk][ty * 4 + i];
            #pragma unroll
            for (int j = 0; j < 4; j++) bb[j] = Bs[kk][tx * 4 + j];
            #pragma unroll
            for (int i = 0; i < 4; i++)
                #pragma unroll
                for (int j = 0; j < 4; j++) acc[i][j] += a[i] * bb[j];
        }
        __syncthreads();
    }
    #pragma unroll
    for (int i = 0; i < 4; i++)
        #pragma unroll
        for (int j = 0; j < 4; j++)
            C[(size_t)(m0 + ty * 4 + i) * QD + n0 + tx * 4 + j] = acc[i][j];
}

// ---------------- router: logits -> softmax -> top2 -> normalized weights ------
__global__ void router_kernel(const float* __restrict__ x, const float* __restrict__ rw,
                              int* __restrict__ topi, float* __restrict__ topw,
                              int* __restrict__ counts)
{
    int t = blockIdx.x;
    const float* row = x + (size_t)t * HH;
    float acc[NE] = {};
    for (int h = threadIdx.x; h < HH; h += 256) {
        float v = row[h];
        const float* r = rw + (size_t)h * NE;
        #pragma unroll
        for (int e = 0; e < NE; e++) acc[e] += v * r[e];
    }
    __shared__ float red[256];
    __shared__ float logits[NE];
    for (int e = 0; e < NE; e++) {
        red[threadIdx.x] = acc[e]; __syncthreads();
        for (int s = 128; s > 0; s >>= 1) {
            if (threadIdx.x < s) red[threadIdx.x] += red[threadIdx.x + s];
            __syncthreads();
        }
        if (threadIdx.x == 0) logits[e] = red[0];
        __syncthreads();
    }
    if (threadIdx.x == 0) {
        float mx = logits[0];
        for (int e = 1; e < NE; e++) mx = fmaxf(mx, logits[e]);
        float p[NE];
        for (int e = 0; e < NE; e++) p[e] = expf(logits[e] - mx);
        int i1 = 0;
        for (int e = 1; e < NE; e++) if (p[e] > p[i1]) i1 = e;
        int i2 = (i1 == 0) ? 1 : 0;
        for (int e = 0; e < NE; e++) if (e != i1 && p[e] > p[i2]) i2 = e;
        float w1 = p[i1], w2 = p[i2];
        float inv = 1.f / (w1 + w2);
        topi[t * 2] = i1;  topi[t * 2 + 1] = i2;
        topw[t * 2] = w1 * inv;  topw[t * 2 + 1] = w2 * inv;
        atomicAdd(&counts[i1], 1);
        atomicAdd(&counts[i2], 1);
    }
}

__global__ void scan_kernel(const int* __restrict__ counts, int* __restrict__ offsets,
                            int* __restrict__ cursor) {
    if (threadIdx.x == 0) {
        int o = 0;
        for (int e = 0; e < NE; e++) { offsets[e] = o; cursor[e] = o; o += counts[e]; }
    }
}

__global__ void scatter_kernel(const int* __restrict__ topi, int* __restrict__ cursor,
                               int* __restrict__ tok, int* __restrict__ slot) {
    int t = blockIdx.x * blockDim.x + threadIdx.x;
    if (t >= TT) return;
    for (int j = 0; j < 2; j++) {
        int e = topi[t * 2 + j];
        int s = atomicAdd(&cursor[e], 1);
        tok[s] = t;
        slot[t * 2 + j] = s;
    }
}

// ---------------- MoE gate+up fused: act = silu(x@Wg) * (x@Wu) ----------------
__global__ __launch_bounds__(256) void gemm_gateup_kernel(
    const float* __restrict__ x, const float* __restrict__ gate_w, const float* __restrict__ up_w,
    const int* __restrict__ tok, const int* __restrict__ offsets, const int* __restrict__ counts,
    float* __restrict__ act)
{
    int e = blockIdx.z;
    int cnt = counts[e];
    int m0 = blockIdx.y * 64;
    if (m0 >= cnt) return;
    int off = offsets[e];
    int n0 = blockIdx.x * 64;
    const float* Bg = gate_w + (size_t)e * HH * II;
    const float* Bu = up_w   + (size_t)e * HH * II;
    __shared__ float As[16][65];
    __shared__ float Bgs[16][65];
    __shared__ float Bus[16][65];
    __shared__ int toks[64];
    int tid = threadIdx.x;
    if (tid < 64) {
        int r = m0 + tid;
        toks[tid] = (r < cnt) ? tok[off + r] : -1;
    }
    __syncthreads();
    int tx = tid & 15, ty = tid >> 4;
    float accg[4][4] = {}, accu[4][4] = {};
    for (int k0 = 0; k0 < HH; k0 += 16) {
        for (int l = tid; l < 64 * 16; l += 256) {
            int r = l >> 4, kk = l & 15;
            int tt = toks[r];
            As[kk][r] = (tt >= 0) ? x[(size_t)tt * HH + k0 + kk] : 0.f;
        }
        for (int l = tid; l < 16 * 64; l += 256) {
            int kk = l >> 6, c = l & 63;
            size_t bidx = (size_t)(k0 + kk) * II + n0 + c;
            Bgs[kk][c] = Bg[bidx];
            Bus[kk][c] = Bu[bidx];
        }
        __syncthreads();
        #pragma unroll
        for (int kk = 0; kk < 16; kk++) {
            float a[4], bg[4], bu[4];
            #pragma unroll
            for (int i = 0; i < 4; i++) a[i] = As[kk][ty * 4 + i];
            #pragma unroll
            for (int j = 0; j < 4; j++) { bg[j] = Bgs[kk][tx * 4 + j]; bu[j] = Bus[kk][tx * 4 + j]; }
            #pragma unroll
            for (int i = 0; i < 4; i++)
                #pragma unroll
                for (int j = 0; j < 4; j++) {
                    accg[i][j] += a[i] * bg[j];
                    accu[i][j] += a[i] * bu[j];
                }
        }
        __syncthreads();
    }
    #pragma unroll
    for (int i = 0; i < 4; i++) {
        int r = m0 + ty * 4 + i;
        if (r >= cnt) continue;
        int s = off + r;
        #pragma unroll
        for (int j = 0; j < 4; j++) {
            float g = accg[i][j], u = accu[i][j];
            float silu = g / (1.f + expf(-g));
            act[(size_t)s * II + n0 + tx * 4 + j] = silu * u;
        }
    }
}

// ---------------- MoE down: y[slot] = act[slot] @ Wd[e] ------------------------
__global__ __launch_bounds__(256) void gemm_down_kernel(
    const float* __restrict__ act, const float* __restrict__ down_w,
    const int* __restrict__ offsets, const int* __restrict__ counts,
    float* __restrict__ y)
{
    int e = blockIdx.z;
    int cnt = counts[e];
    int m0 = blockIdx.y * 64;
    if (m0 >= cnt) return;
    int off = offsets[e];
    int n0 = blockIdx.x * 64;
    const float* Bm = down_w + (size_t)e * II * HH;
    __shared__ float As[16][65];
    __shared__ float Bs[16][65];
    int tid = threadIdx.x;
    int tx = tid & 15, ty = tid >> 4;
    float acc[4][4] = {};
    for (int k0 = 0; k0 < II; k0 += 16) {
        for (int l = tid; l < 64 * 16; l += 256) {
            int r = l >> 4, kk = l & 15;
            int gr = m0 + r;
            As[kk][r] = (gr < cnt) ? act[(size_t)(off + gr) * II + k0 + kk] : 0.f;
        }
        for (int l = tid; l < 16 * 64; l += 256) {
            int kk = l >> 6, c = l & 63;
            Bs[kk][c] = Bm[(size_t)(k0 + kk) * HH + n0 + c];
        }
        __syncthreads();
        #pragma unroll
        for (int kk = 0; kk < 16; kk++) {
            float a[4], bb[4];
            #pragma unroll
            for (int i = 0; i < 4; i++) a[i] = As[kk][ty * 4 + i];
            #pragma unroll
            for (int j = 0; j < 4; j++) bb[j] = Bs[kk][tx * 4 + j];
            #pragma unroll
            for (int i = 0; i < 4; i++)
                #pragma unroll
                for (int j = 0; j < 4; j++) acc[i][j] += a[i] * bb[j];
        }
        __syncthreads();
    }
    #pragma unroll
    for (int i = 0; i < 4; i++) {
        int r = m0 + ty * 4 + i;
        if (r >= cnt) continue;
        #pragma unroll
        for (int j = 0; j < 4; j++)
            y[(size_t)(off + r) * HH + n0 + tx * 4 + j] = acc[i][j];
    }
}

// ---------------- final combine: out = hid2 + w0*y[s0] + w1*y[s1] --------------
__global__ void combine_kernel(const float* __restrict__ hid2, const float* __restrict__ y,
                               const int* __restrict__ slot, const float* __restrict__ topw,
                               float* __restrict__ out)
{
    size_t idx = (size_t)blockIdx.x * blockDim.x + threadIdx.x;
    int t = (int)(idx >> 11);
    int h = (int)(idx & (HH - 1));
    int s0 = slot[t * 2], s1 = slot[t * 2 + 1];
    float w0 = topw[t * 2], w1 = topw[t * 2 + 1];
    out[idx] = hid2[idx] + w0 * y[(size_t)s0 * HH + h] + w1 * y[(size_t)s1 * HH + h];
}

// ---------------- launch -------------------------------------------------------
extern "C" void kernel_launch(void* const* d_in, const int* in_sizes, int n_in,
                              void* d_out, int out_size)
{
    const float* hs  = (const float*)d_in[0];
    const float* ln1 = (const float*)d_in[1];
    const float* ln2 = (const float*)d_in[2];
    const float* wq  = (const float*)d_in[3];
    const float* wk  = (const float*)d_in[4];
    const float* wv  = (const float*)d_in[5];
    const float* wo  = (const float*)d_in[6];
    const float* rw  = (const float*)d_in[7];
    const float* gw  = (const float*)d_in[8];
    const float* uw  = (const float*)d_in[9];
    const float* dw  = (const float*)d_in[10];
    float* out = (float*)d_out;

    float *px, *pq, *pk, *pv, *pscores, *pattn, *phid2, *pact, *py, *ptopw;
    int *ptopi, *pcounts, *poffsets, *pcursor, *ptok, *pslot;
    cudaGetSymbolAddress((void**)&px, g_x);
    cudaGetSymbolAddress((void**)&pq, g_q);
    cudaGetSymbolAddress((void**)&pk, g_k);
    cudaGetSymbolAddress((void**)&pv, g_v);
    cudaGetSymbolAddress((void**)&pscores, g_scores);
    cudaGetSymbolAddress((void**)&pattn, g_attn);
    cudaGetSymbolAddress((void**)&phid2, g_hid2);
    cudaGetSymbolAddress((void**)&pact, g_act);
    cudaGetSymbolAddress((void**)&py, g_y);
    cudaGetSymbolAddress((void**)&ptopi, g_topi);
    cudaGetSymbolAddress((void**)&ptopw, g_topw);
    cudaGetSymbolAddress((void**)&pcounts, g_counts);
    cudaGetSymbolAddress((void**)&poffsets, g_offsets);
    cudaGetSymbolAddress((void**)&pcursor, g_cursor);
    cudaGetSymbolAddress((void**)&ptok, g_tok);
    cudaGetSymbolAddress((void**)&pslot, g_slot);

    zero_counts_kernel<<<1, 32>>>(pcounts);
    rmsnorm_kernel<<<TT, 256>>>(hs, ln1, px);

    gemm_nn_kernel<<<dim3(QD/64,  TT/64), 256>>>(px, wq, nullptr, pq, TT, QD,  HH);
    gemm_nn_kernel<<<dim3(KVD/64, TT/64), 256>>>(px, wk, nullptr, pk, TT, KVD, HH);
    gemm_nn_kernel<<<dim3(KVD/64, TT/64), 256>>>(px, wv, nullptr, pv, TT, KVD, HH);

    rope_kernel<<<(TT*NH*64)/256, 256>>>(pq, NH, TT*NH*64);
    rope_kernel<<<(TT*NKV*64)/256, 256>>>(pk, NKV, TT*NKV*64);

    gemm_scores_kernel<<<dim3(SS/64, SS/64, BB*NH), 256>>>(pq, pk, pscores);
    softmax_kernel<<<dim3(SS, BB*NH), 256>>>(pscores);
    gemm_pv_kernel<<<dim3(HD/64, SS/64, BB*NH), 256>>>(pscores, pv, pattn);

    gemm_nn_kernel<<<dim3(HH/64, TT/64), 256>>>(pattn, wo, hs, phid2, TT, HH, QD);

    rmsnorm_kernel<<<TT, 256>>>(phid2, ln2, px);
    router_kernel<<<TT, 256>>>(px, rw, ptopi, ptopw, pcounts);
    scan_kernel<<<1, 32>>>(pcounts, poffsets, pcursor);
    scatter_kernel<<<TT/256, 256>>>(ptopi, pcursor, ptok, pslot);

    gemm_gateup_kernel<<<dim3(II/64, TT/64, NE), 256>>>(px, gw, uw, ptok, poffsets, pcounts, pact);
    gemm_down_kernel<<<dim3(HH/64, TT/64, NE), 256>>>(pact, dw, poffsets, pcounts, py);

    combine_kernel<<<(TT*(size_t)HH)/256, 256>>>(phid2, py, pslot, ptopw, out);
}

// round 2
// speedup vs baseline: 1.0095x; 1.0095x over previous
#include <cuda_runtime.h>
#include <cuda_bf16.h>
#include <math.h>

// Problem constants
#define BB 2
#define SS 2048
#define HH 2048
#define NH 16
#define NKV 4
#define HD 128
#define NE 8
#define II 4096
#define TT (BB*SS)          // 4096 tokens
#define QD (NH*HD)          // 2048
#define KVD (NKV*HD)        // 512
#define NSLOTS (TT*2)       // 8192 expert assignments

// ---------------- static scratch (device globals; no runtime alloc allowed) ----
__device__ float g_x[(size_t)TT*HH];            // 32MB  (x_norm, reused for x2_norm)
__device__ float g_q[(size_t)TT*QD];            // 32MB
__device__ float g_k[(size_t)TT*KVD];           // 8MB
__device__ float g_v[(size_t)TT*KVD];           // 8MB
__device__ float g_scores[(size_t)BB*NH*SS*SS]; // 512MB
__device__ float g_attn[(size_t)TT*QD];         // 32MB
__device__ float g_hid2[(size_t)TT*HH];         // 32MB
__device__ float g_act[(size_t)NSLOTS*II];      // 128MB
__device__ float g_y[(size_t)NSLOTS*HH];        // 64MB
__device__ int   g_topi[NSLOTS];
__device__ float g_topw[NSLOTS];
__device__ int   g_counts[NE];
__device__ int   g_offsets[NE];
__device__ int   g_cursor[NE];
__device__ int   g_tok[NSLOTS];   // token id per sorted slot
__device__ int   g_slot[NSLOTS];  // slot per (token, choice)

// ---------------- small kernels ------------------------------------------------
__global__ void zero_counts_kernel(int* counts) {
    if (threadIdx.x < NE) counts[threadIdx.x] = 0;
}

__global__ void rmsnorm_kernel(const float* __restrict__ in, const float* __restrict__ w,
                               float* __restrict__ out) {
    int t = blockIdx.x;
    const float* row = in + (size_t)t * HH;
    float ss = 0.f;
    for (int h = threadIdx.x; h < HH; h += 256) { float v = row[h]; ss += v * v; }
    __shared__ float red[256];
    red[threadIdx.x] = ss; __syncthreads();
    for (int s = 128; s > 0; s >>= 1) {
        if (threadIdx.x < s) red[threadIdx.x] += red[threadIdx.x + s];
        __syncthreads();
    }
    float scale = rsqrtf(red[0] / (float)HH + 1e-5f);
    for (int h = threadIdx.x; h < HH; h += 256)
        out[(size_t)t * HH + h] = row[h] * scale * w[h];
}

__global__ void rope_kernel(float* __restrict__ q, int nheads, int total) {
    int idx = blockIdx.x * blockDim.x + threadIdx.x;
    if (idx >= total) return;
    int d = idx & 63;
    int rest = idx >> 6;
    int head = rest % nheads;
    int t = rest / nheads;
    int s = t & (SS - 1);
    float inv = __powf(10000.f, -(float)d / 64.f);
    float ang = (float)s * inv;
    float c, si; __sincosf(ang, &si, &c);
    size_t base = (size_t)t * nheads * HD + (size_t)head * HD + d;
    float x1 = q[base], x2 = q[base + 64];
    q[base]      = x1 * c - x2 * si;
    q[base + 64] = x2 * c + x1 * si;
}

// ---------------- generic dense GEMM: C = A(MxK) * B(KxN) [+ D] ---------------
__global__ __launch_bounds__(256) void gemm_nn_kernel(
    const float* __restrict__ A, const float* __restrict__ B,
    const float* __restrict__ D, float* __restrict__ C,
    int M, int N, int K)
{
    __shared__ float As[16][65];
    __shared__ float Bs[16][65];
    int tid = threadIdx.x;
    int tx = tid & 15, ty = tid >> 4;
    int m0 = blockIdx.y * 64, n0 = blockIdx.x * 64;
    float acc[4][4] = {};
    for (int k0 = 0; k0 < K; k0 += 16) {
        for (int l = tid; l < 64 * 16; l += 256) {
            int r = l >> 4, kk = l & 15;
            int gm = m0 + r;
            As[kk][r] = (gm < M) ? A[(size_t)gm * K + k0 + kk] : 0.f;
        }
        for (int l = tid; l < 16 * 64; l += 256) {
            int kk = l >> 6, c = l & 63;
            int gn = n0 + c;
            Bs[kk][c] = (gn < N) ? B[(size_t)(k0 + kk) * N + gn] : 0.f;
        }
        __syncthreads();
        #pragma unroll
        for (int kk = 0; kk < 16; kk++) {
            float a[4], b[4];
            #pragma unroll
            for (int i = 0; i < 4; i++) a[i] = As[kk][ty * 4 + i];
            #pragma unroll
            for (int j = 0; j < 4; j++) b[j] = Bs[kk][tx * 4 + j];
            #pragma unroll
            for (int i = 0; i < 4; i++)
                #pragma unroll
                for (int j = 0; j < 4; j++) acc[i][j] += a[i] * b[j];
        }
        __syncthreads();
    }
    #pragma unroll
    for (int i = 0; i < 4; i++) {
        int gm = m0 + ty * 4 + i;
        if (gm >= M) continue;
        #pragma unroll
        for (int j = 0; j < 4; j++) {
            int gn = n0 + tx * 4 + j;
            if (gn < N) {
                float v = acc[i][j];
                if (D) v += D[(size_t)gm * N + gn];
                C[(size_t)gm * N + gn] = v;
            }
        }
    }
}

// ---------------- attention scores: S[b,h,m,n] = sum_d q*k (NT) ----------------
__global__ __launch_bounds__(256) void gemm_scores_kernel(
    const float* __restrict__ q, const float* __restrict__ k, float* __restrict__ scores)
{
    int z = blockIdx.z; int b = z >> 4, h = z & 15;
    int m0 = blockIdx.y * 64, n0 = blockIdx.x * 64;
    if (n0 > m0 + 63) return;  // causal: fully masked tile
    const float* A  = q + (size_t)b * SS * QD + (size_t)h * HD;
    const float* Bm = k + (size_t)b * SS * KVD + (size_t)(h >> 2) * HD;
    float* C = scores + (size_t)z * SS * SS;
    __shared__ float As[16][65];
    __shared__ float Bs[16][65];
    int tid = threadIdx.x;
    int tx = tid & 15, ty = tid >> 4;
    float acc[4][4] = {};
    for (int k0 = 0; k0 < HD; k0 += 16) {
        for (int l = tid; l < 64 * 16; l += 256) {
            int r = l >> 4, kk = l & 15;
            As[kk][r] = A[(size_t)(m0 + r) * QD + k0 + kk];
        }
        for (int l = tid; l < 64 * 16; l += 256) {
            int c = l >> 4, kk = l & 15;
            Bs[kk][c] = Bm[(size_t)(n0 + c) * KVD + k0 + kk];
        }
        __syncthreads();
        #pragma unroll
        for (int kk = 0; kk < 16; kk++) {
            float a[4], bb[4];
            #pragma unroll
            for (int i = 0; i < 4; i++) a[i] = As[kk][ty * 4 + i];
            #pragma unroll
            for (int j = 0; j < 4; j++) bb[j] = Bs[kk][tx * 4 + j];
            #pragma unroll
            for (int i = 0; i < 4; i++)
                #pragma unroll
                for (int j = 0; j < 4; j++) acc[i][j] += a[i] * bb[j];
        }
        __syncthreads();
    }
    #pragma unroll
    for (int i = 0; i < 4; i++)
        #pragma unroll
        for (int j = 0; j < 4; j++)
            C[(size_t)(m0 + ty * 4 + i) * SS + n0 + tx * 4 + j] = acc[i][j];
}

// ---------------- causal row softmax (with 1/sqrt(HD) scale) -------------------
__global__ void softmax_kernel(float* __restrict__ scores) {
    int z = blockIdx.y, m = blockIdx.x;
    float* row = scores + (size_t)z * SS * SS + (size_t)m * SS;
    int n = m + 1;
    const float scale = 0.08838834764831845f; // 1/sqrt(128)
    __shared__ float red[256];
    float mx = -3.4e38f;
    for (int j = threadIdx.x; j < n; j += 256) mx = fmaxf(mx, row[j]);
    red[threadIdx.x] = mx; __syncthreads();
    for (int s = 128; s > 0; s >>= 1) {
        if (threadIdx.x < s) red[threadIdx.x] = fmaxf(red[threadIdx.x], red[threadIdx.x + s]);
        __syncthreads();
    }
    mx = red[0]; __syncthreads();
    float sum = 0.f;
    for (int j = threadIdx.x; j < n; j += 256) {
        float p = expf((row[j] - mx) * scale);
        row[j] = p;
        sum += p;
    }
    red[threadIdx.x] = sum; __syncthreads();
    for (int s = 128; s > 0; s >>= 1) {
        if (threadIdx.x < s) red[threadIdx.x] += red[threadIdx.x + s];
        __syncthreads();
    }
    float inv = 1.f / red[0];
    for (int j = threadIdx.x; j < n; j += 256) row[j] *= inv;
    // zero up to this row's 64-tile boundary so PV's tile-granular K read is safe
    int bound = ((m >> 6) + 1) << 6;
    for (int j = n + threadIdx.x; j < bound; j += 256) row[j] = 0.f;
}

// ---------------- PV: attn[b,m,h,d] = sum_n P[m,n] * v[n,d] (NN, causal-K) -----
__global__ __launch_bounds__(256) void gemm_pv_kernel(
    const float* __restrict__ P, const float* __restrict__ v, float* __restrict__ attn)
{
    int z = blockIdx.z; int b = z >> 4, h = z & 15;
    int m0 = blockIdx.y * 64, n0 = blockIdx.x * 64;
    const float* A  = P + (size_t)z * SS * SS;
    const float* Bm = v + (size_t)b * SS * KVD + (size_t)(h >> 2) * HD;
    float* C = attn + (size_t)b * SS * QD + (size_t)h * HD;
    int kend = m0 + 64;  // causal: keys beyond this tile are zero
    __shared__ float As[16][65];
    __shared__ float Bs[16][65];
    int tid = threadIdx.x;
    int tx = tid & 15, ty = tid >> 4;
    float acc[4][4] = {};
    for (int k0 = 0; k0 < kend; k0 += 16) {
        for (int l = tid; l < 64 * 16; l += 256) {
            int r = l >> 4, kk = l & 15;
            As[kk][r] = A[(size_t)(m0 + r) * SS + k0 + kk];
        }
        for (int l = tid; l < 16 * 64; l += 256) {
            int kk = l >> 6, c = l & 63;
            Bs[kk][c] = Bm[(size_t)(k0 + kk) * KVD + n0 + c];
        }
        __syncthreads();
        #pragma unroll
        for (int kk = 0; kk < 16; kk++) {
            float a[4], bb[4];
            #pragma unroll
            for (int i = 0; i < 4; i++) a[i] = As[kk][ty * 4 + i];
            #pragma unroll
            for (int j = 0; j < 4; j++) bb[j] = Bs[kk][tx * 4 + j];
            #pragma unroll
            for (int i = 0; i < 4; i++)
                #pragma unroll
                for (int j = 0; j < 4; j++) acc[i][j] += a[i] * bb[j];
        }
        __syncthreads();
    }
    #pragma unroll
    for (int i = 0; i < 4; i++)
        #pragma unroll
        for (int j = 0; j < 4; j++)
            C[(size_t)(m0 + ty * 4 + i) * QD + n0 + tx * 4 + j] = acc[i][j];
}

// ---------------- router: logits -> softmax -> top2 -> normalized weights ------
__global__ void router_kernel(const float* __restrict__ x, const float* __restrict__ rw,
                              int* __restrict__ topi, float* __restrict__ topw,
                              int* __restrict__ counts)
{
    int t = blockIdx.x;
    const float* row = x + (size_t)t * HH;
    float acc[NE] = {};
    for (int h = threadIdx.x; h < HH; h += 256) {
        float v = row[h];
        const float* r = rw + (size_t)h * NE;
        #pragma unroll
        for (int e = 0; e < NE; e++) acc[e] += v * r[e];
    }
    __shared__ float red[256];
    __shared__ float logits[NE];
    for (int e = 0; e < NE; e++) {
        red[threadIdx.x] = acc[e]; __syncthreads();
        for (int s = 128; s > 0; s >>= 1) {
            if (threadIdx.x < s) red[threadIdx.x] += red[threadIdx.x + s];
            __syncthreads();
        }
        if (threadIdx.x == 0) logits[e] = red[0];
        __syncthreads();
    }
    if (threadIdx.x == 0) {
        float mx = logits[0];
        for (int e = 1; e < NE; e++) mx = fmaxf(mx, logits[e]);
        float p[NE];
        for (int e = 0; e < NE; e++) p[e] = expf(logits[e] - mx);
        int i1 = 0;
        for (int e = 1; e < NE; e++) if (p[e] > p[i1]) i1 = e;
        int i2 = (i1 == 0) ? 1 : 0;
        for (int e = 0; e < NE; e++) if (e != i1 && p[e] > p[i2]) i2 = e;
        float w1 = p[i1], w2 = p[i2];
        float inv = 1.f / (w1 + w2);
        topi[t * 2] = i1;  topi[t * 2 + 1] = i2;
        topw[t * 2] = w1 * inv;  topw[t * 2 + 1] = w2 * inv;
        atomicAdd(&counts[i1], 1);
        atomicAdd(&counts[i2], 1);
    }
}

__global__ void scan_kernel(const int* __restrict__ counts, int* __restrict__ offsets,
                            int* __restrict__ cursor) {
    if (threadIdx.x == 0) {
        int o = 0;
        for (int e = 0; e < NE; e++) { offsets[e] = o; cursor[e] = o; o += counts[e]; }
    }
}

__global__ void scatter_kernel(const int* __restrict__ topi, int* __restrict__ cursor,
                               int* __restrict__ tok, int* __restrict__ slot) {
    int t = blockIdx.x * blockDim.x + threadIdx.x;
    if (t >= TT) return;
    for (int j = 0; j < 2; j++) {
        int e = topi[t * 2 + j];
        int s = atomicAdd(&cursor[e], 1);
        tok[s] = t;
        slot[t * 2 + j] = s;
    }
}

// ---------------- MoE gate+up fused: act = silu(x@Wg) * (x@Wu) ----------------
__global__ __launch_bounds__(256) void gemm_gateup_kernel(
    const float* __restrict__ x, const float* __restrict__ gate_w, const float* __restrict__ up_w,
    const int* __restrict__ tok, const int* __restrict__ offsets, const int* __restrict__ counts,
    float* __restrict__ act)
{
    int e = blockIdx.z;
    int cnt = counts[e];
    int m0 = blockIdx.y * 64;
    if (m0 >= cnt) return;
    int off = offsets[e];
    int n0 = blockIdx.x * 64;
    const float* Bg = gate_w + (size_t)e * HH * II;
    const float* Bu = up_w   + (size_t)e * HH * II;
    __shared__ float As[16][65];
    __shared__ float Bgs[16][65];
    __shared__ float Bus[16][65];
    __shared__ int toks[64];
    int tid = threadIdx.x;
    if (tid < 64) {
        int r = m0 + tid;
        toks[tid] = (r < cnt) ? tok[off + r] : -1;
    }
    __syncthreads();
    int tx = tid & 15, ty = tid >> 4;
    float accg[4][4] = {}, accu[4][4] = {};
    for (int k0 = 0; k0 < HH; k0 += 16) {
        for (int l = tid; l < 64 * 16; l += 256) {
            int r = l >> 4, kk = l & 15;
            int tt = toks[r];
            As[kk][r] = (tt >= 0) ? x[(size_t)tt * HH + k0 + kk] : 0.f;
        }
        for (int l = tid; l < 16 * 64; l += 256) {
            int kk = l >> 6, c = l & 63;
            size_t bidx = (size_t)(k0 + kk) * II + n0 + c;
            Bgs[kk][c] = Bg[bidx];
            Bus[kk][c] = Bu[bidx];
        }
        __syncthreads();
        #pragma unroll
        for (int kk = 0; kk < 16; kk++) {
            float a[4], bg[4], bu[4];
            #pragma unroll
            for (int i = 0; i < 4; i++) a[i] = As[kk][ty * 4 + i];
            #pragma unroll
            for (int j = 0; j < 4; j++) { bg[j] = Bgs[kk][tx * 4 + j]; bu[j] = Bus[kk][tx * 4 + j]; }
            #pragma unroll
            for (int i = 0; i < 4; i++)
                #pragma unroll
                for (int j = 0; j < 4; j++) {
                    accg[i][j] += a[i] * bg[j];
                    accu[i][j] += a[i] * bu[j];
                }
        }
        __syncthreads();
    }
    #pragma unroll
    for (int i = 0; i < 4; i++) {
        int r = m0 + ty * 4 + i;
        if (r >= cnt) continue;
        int s = off + r;
        #pragma unroll
        for (int j = 0; j < 4; j++) {
            float g = accg[i][j], u = accu[i][j];
            float silu = g / (1.f + expf(-g));
            act[(size_t)s * II + n0 + tx * 4 + j] = silu * u;
        }
    }
}

// ---------------- MoE down: y[slot] = act[slot] @ Wd[e] ------------------------
__global__ __launch_bounds__(256) void gemm_down_kernel(
    const float* __restrict__ act, const float* __restrict__ down_w,
    const int* __restrict__ offsets, const int* __restrict__ counts,
    float* __restrict__ y)
{
    int e = blockIdx.z;
    int cnt = counts[e];
    int m0 = blockIdx.y * 64;
    if (m0 >= cnt) return;
    int off = offsets[e];
    int n0 = blockIdx.x * 64;
    const float* Bm = down_w + (size_t)e * II * HH;
    __shared__ float As[16][65];
    __shared__ float Bs[16][65];
    int tid = threadIdx.x;
    int tx = tid & 15, ty = tid >> 4;
    float acc[4][4] = {};
    for (int k0 = 0; k0 < II; k0 += 16) {
        for (int l = tid; l < 64 * 16; l += 256) {
            int r = l >> 4, kk = l & 15;
            int gr = m0 + r;
            As[kk][r] = (gr < cnt) ? act[(size_t)(off + gr) * II + k0 + kk] : 0.f;
        }
        for (int l = tid; l < 16 * 64; l += 256) {
            int kk = l >> 6, c = l & 63;
            Bs[kk][c] = Bm[(size_t)(k0 + kk) * HH + n0 + c];
        }
        __syncthreads();
        #pragma unroll
        for (int kk = 0; kk < 16; kk++) {
            float a[4], bb[4];
            #pragma unroll
            for (int i = 0; i < 4; i++) a[i] = As[kk][ty * 4 + i];
            #pragma unroll
            for (int j = 0; j < 4; j++) bb[j] = Bs[kk][tx * 4 + j];
            #pragma unroll
            for (int i = 0; i < 4; i++)
                #pragma unroll
                for (int j = 0; j < 4; j++) acc[i][j] += a[i] * bb[j];
        }
        __syncthreads();
    }
    #pragma unroll
    for (int i = 0; i < 4; i++) {
        int r = m0 + ty * 4 + i;
        if (r >= cnt) continue;
        #pragma unroll
        for (int j = 0; j < 4; j++)
            y[(size_t)(off + r) * HH + n0 + tx * 4 + j] = acc[i][j];
    }
}

// ---------------- final combine: out = hid2 + w0*y[s0] + w1*y[s1] --------------
__global__ void combine_kernel(const float* __restrict__ hid2, const float* __restrict__ y,
                               const int* __restrict__ slot, const float* __restrict__ topw,
                               float* __restrict__ out)
{
    size_t idx = (size_t)blockIdx.x * blockDim.x + threadIdx.x;
    int t = (int)(idx >> 11);
    int h = (int)(idx & (HH - 1));
    int s0 = slot[t * 2], s1 = slot[t * 2 + 1];
    float w0 = topw[t * 2], w1 = topw[t * 2 + 1];
    out[idx] = hid2[idx] + w0 * y[(size_t)s0 * HH + h] + w1 * y[(size_t)s1 * HH + h];
}

// ---------------- launch -------------------------------------------------------
extern "C" void kernel_launch(void* const* d_in, const int* in_sizes, int n_in,
                              void* d_out, int out_size)
{
    const float* hs  = (const float*)d_in[0];
    const float* ln1 = (const float*)d_in[1];
    const float* ln2 = (const float*)d_in[2];
    const float* wq  = (const float*)d_in[3];
    const float* wk  = (const float*)d_in[4];
    const float* wv  = (const float*)d_in[5];
    const float* wo  = (const float*)d_in[6];
    const float* rw  = (const float*)d_in[7];
    const float* gw  = (const float*)d_in[8];
    const float* uw  = (const float*)d_in[9];
    const float* dw  = (const float*)d_in[10];
    float* out = (float*)d_out;

    float *px, *pq, *pk, *pv, *pscores, *pattn, *phid2, *pact, *py, *ptopw;
    int *ptopi, *pcounts, *poffsets, *pcursor, *ptok, *pslot;
    cudaGetSymbolAddress((void**)&px, g_x);
    cudaGetSymbolAddress((void**)&pq, g_q);
    cudaGetSymbolAddress((void**)&pk, g_k);
    cudaGetSymbolAddress((void**)&pv, g_v);
    cudaGetSymbolAddress((void**)&pscores, g_scores);
    cudaGetSymbolAddress((void**)&pattn, g_attn);
    cudaGetSymbolAddress((void**)&phid2, g_hid2);
    cudaGetSymbolAddress((void**)&pact, g_act);
    cudaGetSymbolAddress((void**)&py, g_y);
    cudaGetSymbolAddress((void**)&ptopi, g_topi);
    cudaGetSymbolAddress((void**)&ptopw, g_topw);
    cudaGetSymbolAddress((void**)&pcounts, g_counts);
    cudaGetSymbolAddress((void**)&poffsets, g_offsets);
    cudaGetSymbolAddress((void**)&pcursor, g_cursor);
    cudaGetSymbolAddress((void**)&ptok, g_tok);
    cudaGetSymbolAddress((void**)&pslot, g_slot);

    zero_counts_kernel<<<1, 32>>>(pcounts);
    rmsnorm_kernel<<<TT, 256>>>(hs, ln1, px);

    gemm_nn_kernel<<<dim3(QD/64,  TT/64), 256>>>(px, wq, nullptr, pq, TT, QD,  HH);
    gemm_nn_kernel<<<dim3(KVD/64, TT/64), 256>>>(px, wk, nullptr, pk, TT, KVD, HH);
    gemm_nn_kernel<<<dim3(KVD/64, TT/64), 256>>>(px, wv, nullptr, pv, TT, KVD, HH);

    rope_kernel<<<(TT*NH*64)/256, 256>>>(pq, NH, TT*NH*64);
    rope_kernel<<<(TT*NKV*64)/256, 256>>>(pk, NKV, TT*NKV*64);

    gemm_scores_kernel<<<dim3(SS/64, SS/64, BB*NH), 256>>>(pq, pk, pscores);
    softmax_kernel<<<dim3(SS, BB*NH), 256>>>(pscores);
    gemm_pv_kernel<<<dim3(HD/64, SS/64, BB*NH), 256>>>(pscores, pv, pattn);

    gemm_nn_kernel<<<dim3(HH/64, TT/64), 256>>>(pattn, wo, hs, phid2, TT, HH, QD);

    rmsnorm_kernel<<<TT, 256>>>(phid2, ln2, px);
    router_kernel<<<TT, 256>>>(px, rw, ptopi, ptopw, pcounts);
    scan_kernel<<<1, 32>>>(pcounts, poffsets, pcursor);
    scatter_kernel<<<TT/256, 256>>>(ptopi, pcursor, ptok, pslot);

    gemm_gateup_kernel<<<dim3(II/64, TT/64, NE), 256>>>(px, gw, uw, ptok, poffsets, pcounts, pact);
    gemm_down_kernel<<<dim3(HH/64, TT/64, NE), 256>>>(pact, dw, poffsets, pcounts, py);

    combine_kernel<<<(TT*(size_t)HH)/256, 256>>>(phid2, py, pslot, ptopw, out);
}

// round 3
// speedup vs baseline: 1.2700x; 1.2581x over previous
#include <cuda_runtime.h>
#include <cuda_bf16.h>
#include <math.h>

// Problem constants
#define BB 2
#define SS 2048
#define HH 2048
#define NH 16
#define NKV 4
#define HD 128
#define NE 8
#define II 4096
#define TT (BB*SS)          // 4096 tokens
#define QD (NH*HD)          // 2048
#define KVD (NKV*HD)        // 512
#define NSLOTS (TT*2)       // 8192 expert assignments

typedef unsigned long long ull;

// ---------------- static scratch ----------------------------------------------
__device__ float g_x[(size_t)TT*HH];            // 32MB
__device__ float g_q[(size_t)TT*QD];            // 32MB
__device__ float g_k[(size_t)TT*KVD];           // 8MB
__device__ float g_v[(size_t)TT*KVD];           // 8MB
__device__ float g_scores[(size_t)BB*NH*SS*SS]; // 512MB
__device__ float g_attn[(size_t)TT*QD];         // 32MB
__device__ float g_hid2[(size_t)TT*HH];         // 32MB
__device__ float g_xg[(size_t)NSLOTS*HH];       // 64MB  gathered tokens
__device__ float g_g[(size_t)NSLOTS*II];        // 128MB gate out -> act
__device__ float g_u[(size_t)NSLOTS*II];        // 128MB up out
__device__ float g_y[(size_t)NSLOTS*HH];        // 64MB
__device__ int   g_topi[NSLOTS];
__device__ float g_topw[NSLOTS];
__device__ int   g_counts[NE];
__device__ int   g_offsets[NE];
__device__ int   g_cursor[NE];
__device__ int   g_tok[NSLOTS];
__device__ int   g_slot[NSLOTS];

// ---------------- packed f32x2 helpers ----------------------------------------
__device__ __forceinline__ ull pack2(float x) {
    ull r; asm("mov.b64 %0, {%1, %1};" : "=l"(r) : "f"(x)); return r;
}
__device__ __forceinline__ ull fma2(ull a, ull b, ull c) {
    ull d; asm("fma.rn.f32x2 %0, %1, %2, %3;" : "=l"(d) : "l"(a), "l"(b), "l"(c)); return d;
}
__device__ __forceinline__ void unpack2(ull v, float& lo, float& hi) {
    asm("mov.b64 {%0, %1}, %2;" : "=f"(lo), "=f"(hi) : "l"(v));
}

// ---------------- SGEMM core: 128x128 tile, BK=8, double buffered --------------
// BT=false: B is [K x 128] row-major with stride ldb (tile base already at n0).
// BT=true : B is [128 x K] row-major with stride ldb (rows = n index).
template<bool BT>
__device__ __forceinline__ void sgemm_core(
    const float* __restrict__ A, int lda,
    const float* __restrict__ B, int ldb,
    const float* __restrict__ D,
    float* __restrict__ C, int ldc,
    int Mrem, int K)
{
    __shared__ float As[2][8][132];
    __shared__ float Bs[2][8][132];
    int tid = threadIdx.x;
    int tx = tid & 15, ty = tid >> 4;

    int ar = tid >> 1;            // 0..127  (A rows / BT-B rows)
    int ac = (tid & 1) * 4;       // 0 or 4  (K offset)
    int br = tid >> 5;            // 0..7    (NN-B k row)
    int bc = (tid & 31) * 4;      // 0..124  (NN-B col)

    ull acc[8][4];
    #pragma unroll
    for (int i = 0; i < 8; i++)
        #pragma unroll
        for (int j = 0; j < 4; j++) acc[i][j] = 0ull;

    int KT = K >> 3;

    float4 ra, rb;
    ra = (ar < Mrem) ? *(const float4*)(A + (size_t)ar * lda + ac)
                     : make_float4(0.f, 0.f, 0.f, 0.f);
    if (BT) rb = *(const float4*)(B + (size_t)ar * ldb + ac);
    else    rb = *(const float4*)(B + (size_t)br * ldb + bc);

    As[0][ac+0][ar] = ra.x; As[0][ac+1][ar] = ra.y;
    As[0][ac+2][ar] = ra.z; As[0][ac+3][ar] = ra.w;
    if (BT) {
        Bs[0][ac+0][ar] = rb.x; Bs[0][ac+1][ar] = rb.y;
        Bs[0][ac+2][ar] = rb.z; Bs[0][ac+3][ar] = rb.w;
    } else {
        *(float4*)&Bs[0][br][bc] = rb;
    }
    __syncthreads();

    for (int kt = 0; kt < KT; kt++) {
        int cur = kt & 1;
        int k0n = (kt + 1) << 3;
        if (kt + 1 < KT) {
            ra = (ar < Mrem) ? *(const float4*)(A + (size_t)ar * lda + k0n + ac)
                             : make_float4(0.f, 0.f, 0.f, 0.f);
            if (BT) rb = *(const float4*)(B + (size_t)ar * ldb + k0n + ac);
            else    rb = *(const float4*)(B + (size_t)(k0n + br) * ldb + bc);
        }
        #pragma unroll
        for (int kk = 0; kk < 8; kk++) {
            float4 a0 = *(const float4*)&As[cur][kk][ty * 8];
            float4 a1 = *(const float4*)&As[cur][kk][ty * 8 + 4];
            const ull* bp = (const ull*)&Bs[cur][kk][tx * 8];
            ull b0 = bp[0], b1 = bp[1], b2 = bp[2], b3 = bp[3];
            float av[8] = {a0.x, a0.y, a0.z, a0.w, a1.x, a1.y, a1.z, a1.w};
            #pragma unroll
            for (int i = 0; i < 8; i++) {
                ull aa = pack2(av[i]);
                acc[i][0] = fma2(aa, b0, acc[i][0]);
                acc[i][1] = fma2(aa, b1, acc[i][1]);
                acc[i][2] = fma2(aa, b2, acc[i][2]);
                acc[i][3] = fma2(aa, b3, acc[i][3]);
            }
        }
        if (kt + 1 < KT) {
            int nxt = cur ^ 1;
            As[nxt][ac+0][ar] = ra.x; As[nxt][ac+1][ar] = ra.y;
            As[nxt][ac+2][ar] = ra.z; As[nxt][ac+3][ar] = ra.w;
            if (BT) {
                Bs[nxt][ac+0][ar] = rb.x; Bs[nxt][ac+1][ar] = rb.y;
                Bs[nxt][ac+2][ar] = rb.z; Bs[nxt][ac+3][ar] = rb.w;
            } else {
                *(float4*)&Bs[nxt][br][bc] = rb;
            }
            __syncthreads();
        }
    }

    #pragma unroll
    for (int i = 0; i < 8; i++) {
        int r = ty * 8 + i;
        if (r >= Mrem) continue;
        float o[8];
        #pragma unroll
        for (int j = 0; j < 4; j++) unpack2(acc[i][j], o[2*j], o[2*j+1]);
        float* crow = C + (size_t)r * ldc + tx * 8;
        if (D) {
            const float* drow = D + (size_t)r * ldc + tx * 8;
            float4 d0 = *(const float4*)drow;
            float4 d1 = *(const float4*)(drow + 4);
            o[0] += d0.x; o[1] += d0.y; o[2] += d0.z; o[3] += d0.w;
            o[4] += d1.x; o[5] += d1.y; o[6] += d1.z; o[7] += d1.w;
        }
        *(float4*)crow       = make_float4(o[0], o[1], o[2], o[3]);
        *(float4*)(crow + 4) = make_float4(o[4], o[5], o[6], o[7]);
    }
}

// ---------------- GEMM wrappers ------------------------------------------------
__global__ __launch_bounds__(256) void sgemm_nn_kernel(
    const float* __restrict__ A, const float* __restrict__ B,
    const float* __restrict__ D, float* __restrict__ C, int M, int N, int K)
{
    int m0 = blockIdx.y * 128, n0 = blockIdx.x * 128;
    sgemm_core<false>(A + (size_t)m0 * K, K, B + n0, N,
                      D ? D + (size_t)m0 * N + n0 : (const float*)0,
                      C + (size_t)m0 * N + n0, N, M - m0, K);
}

__global__ __launch_bounds__(256) void sgemm_scores_kernel(
    const float* __restrict__ q, const float* __restrict__ k, float* __restrict__ scores)
{
    int z = blockIdx.z, b = z >> 4, h = z & 15;
    int m0 = blockIdx.y * 128, n0 = blockIdx.x * 128;
    if (n0 >= m0 + 128) return;  // causal tile skip
    const float* A  = q + (size_t)b * SS * QD + (size_t)h * HD + (size_t)m0 * QD;
    const float* Bp = k + (size_t)b * SS * KVD + (size_t)(h >> 2) * HD + (size_t)n0 * KVD;
    float* C = scores + (size_t)z * SS * SS + (size_t)m0 * SS + n0;
    sgemm_core<true>(A, QD, Bp, KVD, (const float*)0, C, SS, 128, HD);
}

__global__ __launch_bounds__(256) void sgemm_pv_kernel(
    const float* __restrict__ P, const float* __restrict__ v, float* __restrict__ attn)
{
    int z = blockIdx.z, b = z >> 4, h = z & 15;
    int m0 = blockIdx.y * 128;
    const float* A  = P + (size_t)z * SS * SS + (size_t)m0 * SS;
    const float* Bp = v + (size_t)b * SS * KVD + (size_t)(h >> 2) * HD;
    float* C = attn + (size_t)b * SS * QD + (size_t)h * HD + (size_t)m0 * QD;
    sgemm_core<false>(A, SS, Bp, KVD, (const float*)0, C, QD, 128, m0 + 128);
}

__global__ __launch_bounds__(256) void sgemm_moe_kernel(
    const float* __restrict__ Ab, const float* __restrict__ W, float* __restrict__ out,
    const int* __restrict__ offsets, const int* __restrict__ counts, int N, int K)
{
    int e = blockIdx.z;
    int cnt = counts[e];
    int m0 = blockIdx.y * 128;
    if (m0 >= cnt) return;
    int off = offsets[e];
    int n0 = blockIdx.x * 128;
    sgemm_core<false>(Ab + ((size_t)off + m0) * K, K,
                      W + (size_t)e * K * N + n0, N, (const float*)0,
                      out + ((size_t)off + m0) * N + n0, N, cnt - m0, K);
}

// ---------------- small kernels ------------------------------------------------
__global__ void zero_counts_kernel(int* counts) {
    if (threadIdx.x < NE) counts[threadIdx.x] = 0;
}

__global__ void rmsnorm_kernel(const float* __restrict__ in, const float* __restrict__ w,
                               float* __restrict__ out) {
    int t = blockIdx.x;
    const float* row = in + (size_t)t * HH;
    float ss = 0.f;
    for (int h = threadIdx.x; h < HH; h += 256) { float v = row[h]; ss += v * v; }
    __shared__ float red[256];
    red[threadIdx.x] = ss; __syncthreads();
    for (int s = 128; s > 0; s >>= 1) {
        if (threadIdx.x < s) red[threadIdx.x] += red[threadIdx.x + s];
        __syncthreads();
    }
    float scale = rsqrtf(red[0] / (float)HH + 1e-5f);
    for (int h = threadIdx.x; h < HH; h += 256)
        out[(size_t)t * HH + h] = row[h] * scale * w[h];
}

__global__ void rope_kernel(float* __restrict__ q, int nheads, int total) {
    int idx = blockIdx.x * blockDim.x + threadIdx.x;
    if (idx >= total) return;
    int d = idx & 63;
    int rest = idx >> 6;
    int head = rest % nheads;
    int t = rest / nheads;
    int s = t & (SS - 1);
    float inv = __powf(10000.f, -(float)d / 64.f);
    float ang = (float)s * inv;
    float c, si; __sincosf(ang, &si, &c);
    size_t base = (size_t)t * nheads * HD + (size_t)head * HD + d;
    float x1 = q[base], x2 = q[base + 64];
    q[base]      = x1 * c - x2 * si;
    q[base + 64] = x2 * c + x1 * si;
}

__global__ void softmax_kernel(float* __restrict__ scores) {
    int z = blockIdx.y, m = blockIdx.x;
    float* row = scores + (size_t)z * SS * SS + (size_t)m * SS;
    int n = m + 1;
    const float scale = 0.08838834764831845f; // 1/sqrt(128)
    __shared__ float red[256];
    float mx = -3.4e38f;
    for (int j = threadIdx.x; j < n; j += 256) mx = fmaxf(mx, row[j]);
    red[threadIdx.x] = mx; __syncthreads();
    for (int s = 128; s > 0; s >>= 1) {
        if (threadIdx.x < s) red[threadIdx.x] = fmaxf(red[threadIdx.x], red[threadIdx.x + s]);
        __syncthreads();
    }
    mx = red[0]; __syncthreads();
    float sum = 0.f;
    for (int j = threadIdx.x; j < n; j += 256) {
        float p = expf((row[j] - mx) * scale);
        row[j] = p;
        sum += p;
    }
    red[threadIdx.x] = sum; __syncthreads();
    for (int s = 128; s > 0; s >>= 1) {
        if (threadIdx.x < s) red[threadIdx.x] += red[threadIdx.x + s];
        __syncthreads();
    }
    float inv = 1.f / red[0];
    for (int j = threadIdx.x; j < n; j += 256) row[j] *= inv;
    // zero up to the 128-tile boundary so PV's tile-granular K read is safe
    int bound = ((m >> 7) + 1) << 7;
    for (int j = n + threadIdx.x; j < bound; j += 256) row[j] = 0.f;
}

__global__ void router_kernel(const float* __restrict__ x, const float* __restrict__ rw,
                              int* __restrict__ topi, float* __restrict__ topw,
                              int* __restrict__ counts)
{
    int t = blockIdx.x;
    const float* row = x + (size_t)t * HH;
    float acc[NE] = {};
    for (int h = threadIdx.x; h < HH; h += 256) {
        float v = row[h];
        const float* r = rw + (size_t)h * NE;
        #pragma unroll
        for (int e = 0; e < NE; e++) acc[e] += v * r[e];
    }
    __shared__ float red[256];
    __shared__ float logits[NE];
    for (int e = 0; e < NE; e++) {
        red[threadIdx.x] = acc[e]; __syncthreads();
        for (int s = 128; s > 0; s >>= 1) {
            if (threadIdx.x < s) red[threadIdx.x] += red[threadIdx.x + s];
            __syncthreads();
        }
        if (threadIdx.x == 0) logits[e] = red[0];
        __syncthreads();
    }
    if (threadIdx.x == 0) {
        float mx = logits[0];
        for (int e = 1; e < NE; e++) mx = fmaxf(mx, logits[e]);
        float p[NE];
        for (int e = 0; e < NE; e++) p[e] = expf(logits[e] - mx);
        int i1 = 0;
        for (int e = 1; e < NE; e++) if (p[e] > p[i1]) i1 = e;
        int i2 = (i1 == 0) ? 1 : 0;
        for (int e = 0; e < NE; e++) if (e != i1 && p[e] > p[i2]) i2 = e;
        float w1 = p[i1], w2 = p[i2];
        float inv = 1.f / (w1 + w2);
        topi[t * 2] = i1;  topi[t * 2 + 1] = i2;
        topw[t * 2] = w1 * inv;  topw[t * 2 + 1] = w2 * inv;
        atomicAdd(&counts[i1], 1);
        atomicAdd(&counts[i2], 1);
    }
}

__global__ void scan_kernel(const int* __restrict__ counts, int* __restrict__ offsets,
                            int* __restrict__ cursor) {
    if (threadIdx.x == 0) {
        int o = 0;
        for (int e = 0; e < NE; e++) { offsets[e] = o; cursor[e] = o; o += counts[e]; }
    }
}

__global__ void scatter_kernel(const int* __restrict__ topi, int* __restrict__ cursor,
                               int* __restrict__ tok, int* __restrict__ slot) {
    int t = blockIdx.x * blockDim.x + threadIdx.x;
    if (t >= TT) return;
    for (int j = 0; j < 2; j++) {
        int e = topi[t * 2 + j];
        int s = atomicAdd(&cursor[e], 1);
        tok[s] = t;
        slot[t * 2 + j] = s;
    }
}

__global__ void gather_kernel(const float* __restrict__ x, const int* __restrict__ tok,
                              float* __restrict__ xg) {
    size_t idx = (size_t)blockIdx.x * blockDim.x + threadIdx.x;
    int slot = (int)(idx >> 11);
    int h = (int)(idx & (HH - 1));
    xg[idx] = x[(size_t)tok[slot] * HH + h];
}

__global__ void silu_mul_kernel(const float* __restrict__ g, const float* __restrict__ u,
                                float* __restrict__ act) {
    size_t idx = (size_t)blockIdx.x * blockDim.x + threadIdx.x;
    float gv = g[idx], uv = u[idx];
    act[idx] = gv / (1.f + expf(-gv)) * uv;
}

__global__ void combine_kernel(const float* __restrict__ hid2, const float* __restrict__ y,
                               const int* __restrict__ slot, const float* __restrict__ topw,
                               float* __restrict__ out)
{
    size_t idx = (size_t)blockIdx.x * blockDim.x + threadIdx.x;
    int t = (int)(idx >> 11);
    int h = (int)(idx & (HH - 1));
    int s0 = slot[t * 2], s1 = slot[t * 2 + 1];
    float w0 = topw[t * 2], w1 = topw[t * 2 + 1];
    out[idx] = hid2[idx] + w0 * y[(size_t)s0 * HH + h] + w1 * y[(size_t)s1 * HH + h];
}

// ---------------- launch -------------------------------------------------------
extern "C" void kernel_launch(void* const* d_in, const int* in_sizes, int n_in,
                              void* d_out, int out_size)
{
    const float* hs  = (const float*)d_in[0];
    const float* ln1 = (const float*)d_in[1];
    const float* ln2 = (const float*)d_in[2];
    const float* wq  = (const float*)d_in[3];
    const float* wk  = (const float*)d_in[4];
    const float* wv  = (const float*)d_in[5];
    const float* wo  = (const float*)d_in[6];
    const float* rw  = (const float*)d_in[7];
    const float* gw  = (const float*)d_in[8];
    const float* uw  = (const float*)d_in[9];
    const float* dw  = (const float*)d_in[10];
    float* out = (float*)d_out;

    float *px, *pq, *pk, *pv, *pscores, *pattn, *phid2, *pxg, *pg, *pu, *py, *ptopw;
    int *ptopi, *pcounts, *poffsets, *pcursor, *ptok, *pslot;
    cudaGetSymbolAddress((void**)&px, g_x);
    cudaGetSymbolAddress((void**)&pq, g_q);
    cudaGetSymbolAddress((void**)&pk, g_k);
    cudaGetSymbolAddress((void**)&pv, g_v);
    cudaGetSymbolAddress((void**)&pscores, g_scores);
    cudaGetSymbolAddress((void**)&pattn, g_attn);
    cudaGetSymbolAddress((void**)&phid2, g_hid2);
    cudaGetSymbolAddress((void**)&pxg, g_xg);
    cudaGetSymbolAddress((void**)&pg, g_g);
    cudaGetSymbolAddress((void**)&pu, g_u);
    cudaGetSymbolAddress((void**)&py, g_y);
    cudaGetSymbolAddress((void**)&ptopi, g_topi);
    cudaGetSymbolAddress((void**)&ptopw, g_topw);
    cudaGetSymbolAddress((void**)&pcounts, g_counts);
    cudaGetSymbolAddress((void**)&poffsets, g_offsets);
    cudaGetSymbolAddress((void**)&pcursor, g_cursor);
    cudaGetSymbolAddress((void**)&ptok, g_tok);
    cudaGetSymbolAddress((void**)&pslot, g_slot);

    zero_counts_kernel<<<1, 32>>>(pcounts);
    rmsnorm_kernel<<<TT, 256>>>(hs, ln1, px);

    sgemm_nn_kernel<<<dim3(QD/128,  TT/128), 256>>>(px, wq, nullptr, pq, TT, QD,  HH);
    sgemm_nn_kernel<<<dim3(KVD/128, TT/128), 256>>>(px, wk, nullptr, pk, TT, KVD, HH);
    sgemm_nn_kernel<<<dim3(KVD/128, TT/128), 256>>>(px, wv, nullptr, pv, TT, KVD, HH);

    rope_kernel<<<(TT*NH*64)/256, 256>>>(pq, NH, TT*NH*64);
    rope_kernel<<<(TT*NKV*64)/256, 256>>>(pk, NKV, TT*NKV*64);

    sgemm_scores_kernel<<<dim3(SS/128, SS/128, BB*NH), 256>>>(pq, pk, pscores);
    softmax_kernel<<<dim3(SS, BB*NH), 256>>>(pscores);
    sgemm_pv_kernel<<<dim3(1, SS/128, BB*NH), 256>>>(pscores, pv, pattn);

    sgemm_nn_kernel<<<dim3(HH/128, TT/128), 256>>>(pattn, wo, hs, phid2, TT, HH, QD);

    rmsnorm_kernel<<<TT, 256>>>(phid2, ln2, px);
    router_kernel<<<TT, 256>>>(px, rw, ptopi, ptopw, pcounts);
    scan_kernel<<<1, 32>>>(pcounts, poffsets, pcursor);
    scatter_kernel<<<TT/256, 256>>>(ptopi, pcursor, ptok, pslot);
    gather_kernel<<<(int)(((size_t)NSLOTS*HH)/256), 256>>>(px, ptok, pxg);

    sgemm_moe_kernel<<<dim3(II/128, NSLOTS/128, NE), 256>>>(pxg, gw, pg, poffsets, pcounts, II, HH);
    sgemm_moe_kernel<<<dim3(II/128, NSLOTS/128, NE), 256>>>(pxg, uw, pu, poffsets, pcounts, II, HH);
    silu_mul_kernel<<<(int)(((size_t)NSLOTS*II)/256), 256>>>(pg, pu, pg);
    sgemm_moe_kernel<<<dim3(HH/128, NSLOTS/128, NE), 256>>>(pg, dw, py, poffsets, pcounts, HH, II);

    combine_kernel<<<(int)(((size_t)TT*HH)/256), 256>>>(phid2, py, pslot, ptopw, out);
}

// round 7
// speedup vs baseline: 2.5236x; 1.9870x over previous
#include <cuda_runtime.h>
#include <cuda_bf16.h>
#include <math.h>
#include <cstdint>

// Problem constants
#define BB 2
#define SS 2048
#define HH 2048
#define NH 16
#define NKV 4
#define HD 128
#define NE 8
#define II 4096
#define TT (BB*SS)          // 4096 tokens
#define QD (NH*HD)          // 2048
#define KVD (NKV*HD)        // 512
#define NSLOTS (TT*2)       // 8192 expert assignments

#define APAD 36             // smem row stride (floats): bank = row*4+k -> conflict free

// ---------------- static scratch ----------------------------------------------
__device__ float g_x[(size_t)TT*HH];
__device__ float g_q[(size_t)TT*QD];
__device__ float g_k[(size_t)TT*KVD];
__device__ float g_v[(size_t)TT*KVD];
__device__ float g_scores[(size_t)BB*NH*SS*SS];
__device__ float g_attn[(size_t)TT*QD];
__device__ float g_hid2[(size_t)TT*HH];
__device__ float g_xg[(size_t)NSLOTS*HH];
__device__ float g_g[(size_t)NSLOTS*II];
__device__ float g_u[(size_t)NSLOTS*II];
__device__ float g_y[(size_t)NSLOTS*HH];
__device__ int   g_topi[NSLOTS];
__device__ float g_topw[NSLOTS];
__device__ int   g_counts[NE];
__device__ int   g_offsets[NE];
__device__ int   g_cursor[NE];
__device__ int   g_tok[NSLOTS];
__device__ int   g_slot[NSLOTS];

// ---------------- tf32 helpers --------------------------------------------------
__device__ __forceinline__ float to_tf32(float x) {
    float r; asm("cvt.rna.tf32.f32 %0, %1;" : "=f"(r) : "f"(x)); return r;
}
__device__ __forceinline__ float4 to_tf32_4(float4 v) {
    return make_float4(to_tf32(v.x), to_tf32(v.y), to_tf32(v.z), to_tf32(v.w));
}
__device__ __forceinline__ void mma_tf32(float* d, const uint32_t* a, const uint32_t* b) {
    asm volatile(
        "mma.sync.aligned.m16n8k8.row.col.f32.tf32.tf32.f32 "
        "{%0,%1,%2,%3}, {%4,%5,%6,%7}, {%8,%9}, {%0,%1,%2,%3};"
        : "+f"(d[0]), "+f"(d[1]), "+f"(d[2]), "+f"(d[3])
        : "r"(a[0]), "r"(a[1]), "r"(a[2]), "r"(a[3]), "r"(b[0]), "r"(b[1]));
}

// ---------------- tf32 MMA GEMM core: 128x128 CTA tile, BK=32, double buffered --
// BDIRECT=true : B is [N,K] row-major (K contiguous), stride ldb (K-major, direct).
// BDIRECT=false: B is [K,N] row-major (N contiguous), stride ldb -> transpose on load.
// SMEM buffers: A[2][128][APAD], B[2][128][APAD] (floats, tf32-rounded)
#define ABUF_FLOATS (128*APAD)
#define TC_SMEM_BYTES (4 * ABUF_FLOATS * 4)   // 2 A bufs + 2 B bufs

template<bool BDIRECT>
__device__ __forceinline__ void mma_core(
    const float* __restrict__ A, int lda, int Mrem,
    const float* __restrict__ B, int ldb,
    const float* __restrict__ D, float* __restrict__ C, int ldc, int K)
{
    extern __shared__ __align__(16) float smemf[];
    float* Abuf[2] = { smemf,                  smemf + ABUF_FLOATS };
    float* Bbuf[2] = { smemf + 2*ABUF_FLOATS,  smemf + 3*ABUF_FLOATS };

    int tid = threadIdx.x;
    int wid = tid >> 5;
    int lane = tid & 31;

    // loader mapping: thread -> (row r, k offset ko) loads 16 floats (4 float4)
    int r  = tid >> 1;            // 0..127
    int ko = (tid & 1) * 16;      // 0 or 16
    // trans-B loader mapping
    int kl = tid >> 5;            // 0..7
    int n4 = (tid & 31) * 4;      // 0..124

    // compute mapping: warp (wid>>2) x (wid&3) -> 64x32 region
    int wm = (wid >> 2) * 64;
    int wn = (wid & 3) * 32;
    int qrow = lane >> 2;         // 0..7
    int kq = lane & 3;            // 0..3

    float acc[4][4][4];
    #pragma unroll
    for (int i = 0; i < 4; i++)
        #pragma unroll
        for (int j = 0; j < 4; j++)
            #pragma unroll
            for (int c = 0; c < 4; c++) acc[i][j][c] = 0.f;

    int KT = K >> 5;

    // ---- load chunk 0 ----
    {
        const float* ap = A + (size_t)r * lda + ko;
        float* as = Abuf[0] + r * APAD + ko;
        #pragma unroll
        for (int j = 0; j < 4; j++) {
            float4 v = (r < Mrem) ? *(const float4*)(ap + j*4) : make_float4(0.f,0.f,0.f,0.f);
            *(float4*)(as + j*4) = to_tf32_4(v);
        }
        if (BDIRECT) {
            const float* bp = B + (size_t)r * ldb + ko;
            float* bs = Bbuf[0] + r * APAD + ko;
            #pragma unroll
            for (int j = 0; j < 4; j++)
                *(float4*)(bs + j*4) = to_tf32_4(*(const float4*)(bp + j*4));
        } else {
            #pragma unroll
            for (int p = 0; p < 4; p++) {
                int kk = kl + p*8;
                float4 v = to_tf32_4(*(const float4*)(B + (size_t)kk * ldb + n4));
                Bbuf[0][(n4+0)*APAD + kk] = v.x;
                Bbuf[0][(n4+1)*APAD + kk] = v.y;
                Bbuf[0][(n4+2)*APAD + kk] = v.z;
                Bbuf[0][(n4+3)*APAD + kk] = v.w;
            }
        }
    }
    __syncthreads();

    for (int kt = 0; kt < KT; kt++) {
        int cur = kt & 1;
        float4 ra[4], rb[4];
        if (kt + 1 < KT) {
            int kc = (kt + 1) << 5;
            const float* ap = A + (size_t)r * lda + kc + ko;
            #pragma unroll
            for (int j = 0; j < 4; j++)
                ra[j] = (r < Mrem) ? *(const float4*)(ap + j*4) : make_float4(0.f,0.f,0.f,0.f);
            if (BDIRECT) {
                const float* bp = B + (size_t)r * ldb + kc + ko;
                #pragma unroll
                for (int j = 0; j < 4; j++) rb[j] = *(const float4*)(bp + j*4);
            } else {
                #pragma unroll
                for (int p = 0; p < 4; p++)
                    rb[p] = *(const float4*)(B + (size_t)(kc + kl + p*8) * ldb + n4);
            }
        }

        // ---- compute on buffer cur: 4 k-steps of k8 ----
        const float* As = Abuf[cur];
        const float* Bs = Bbuf[cur];
        #pragma unroll
        for (int kk = 0; kk < 4; kk++) {
            int kb = kk * 8 + kq;
            uint32_t afr[4][4], bfr[4][2];
            #pragma unroll
            for (int mt = 0; mt < 4; mt++) {
                const float* ab = As + (wm + mt*16 + qrow) * APAD + kb;
                afr[mt][0] = __float_as_uint(ab[0]);
                afr[mt][1] = __float_as_uint(ab[8*APAD]);
                afr[mt][2] = __float_as_uint(ab[4]);
                afr[mt][3] = __float_as_uint(ab[8*APAD + 4]);
            }
            #pragma unroll
            for (int nt = 0; nt < 4; nt++) {
                const float* bb = Bs + (wn + nt*8 + qrow) * APAD + kb;
                bfr[nt][0] = __float_as_uint(bb[0]);
                bfr[nt][1] = __float_as_uint(bb[4]);
            }
            #pragma unroll
            for (int mt = 0; mt < 4; mt++)
                #pragma unroll
                for (int nt = 0; nt < 4; nt++)
                    mma_tf32(acc[mt][nt], afr[mt], bfr[nt]);
        }

        if (kt + 1 < KT) {
            int nxt = cur ^ 1;
            float* as = Abuf[nxt] + r * APAD + ko;
            #pragma unroll
            for (int j = 0; j < 4; j++) *(float4*)(as + j*4) = to_tf32_4(ra[j]);
            if (BDIRECT) {
                float* bs = Bbuf[nxt] + r * APAD + ko;
                #pragma unroll
                for (int j = 0; j < 4; j++) *(float4*)(bs + j*4) = to_tf32_4(rb[j]);
            } else {
                #pragma unroll
                for (int p = 0; p < 4; p++) {
                    int kk = kl + p*8;
                    float4 v = to_tf32_4(rb[p]);
                    Bbuf[nxt][(n4+0)*APAD + kk] = v.x;
                    Bbuf[nxt][(n4+1)*APAD + kk] = v.y;
                    Bbuf[nxt][(n4+2)*APAD + kk] = v.z;
                    Bbuf[nxt][(n4+3)*APAD + kk] = v.w;
                }
            }
            __syncthreads();
        }
    }

    // ---- epilogue ----
    #pragma unroll
    for (int mt = 0; mt < 4; mt++) {
        int r0 = wm + mt*16 + qrow;
        #pragma unroll
        for (int nt = 0; nt < 4; nt++) {
            int c0 = wn + nt*8 + kq*2;
            if (r0 < Mrem) {
                float2 v = make_float2(acc[mt][nt][0], acc[mt][nt][1]);
                if (D) {
                    float2 d = *(const float2*)(D + (size_t)r0 * ldc + c0);
                    v.x += d.x; v.y += d.y;
                }
                *(float2*)(C + (size_t)r0 * ldc + c0) = v;
            }
            int r1 = r0 + 8;
            if (r1 < Mrem) {
                float2 v = make_float2(acc[mt][nt][2], acc[mt][nt][3]);
                if (D) {
                    float2 d = *(const float2*)(D + (size_t)r1 * ldc + c0);
                    v.x += d.x; v.y += d.y;
                }
                *(float2*)(C + (size_t)r1 * ldc + c0) = v;
            }
        }
    }
}

// ---------------- GEMM wrappers ------------------------------------------------
__global__ __launch_bounds__(256, 2)
void tc_gemm_nn(const float* __restrict__ A, const float* __restrict__ B,
                const float* __restrict__ D, float* __restrict__ C, int M, int N, int K)
{
    int m0 = blockIdx.y * 128, n0 = blockIdx.x * 128;
    mma_core<false>(A + (size_t)m0 * K, K, M - m0,
                    B + n0, N,
                    D ? D + (size_t)m0 * N + n0 : (const float*)0,
                    C + (size_t)m0 * N + n0, N, K);
}

__global__ __launch_bounds__(256, 2)
void tc_scores(const float* __restrict__ q, const float* __restrict__ k,
               float* __restrict__ scores)
{
    int z = blockIdx.z, b = z >> 4, h = z & 15;
    int m0 = blockIdx.y * 128, n0 = blockIdx.x * 128;
    if (n0 >= m0 + 128) return;  // causal skip
    const float* A  = q + (size_t)b * SS * QD + (size_t)h * HD + (size_t)m0 * QD;
    const float* Bp = k + (size_t)b * SS * KVD + (size_t)(h >> 2) * HD + (size_t)n0 * KVD;
    float* C = scores + (size_t)z * SS * SS + (size_t)m0 * SS + n0;
    mma_core<true>(A, QD, 128, Bp, KVD, (const float*)0, C, SS, HD);
}

__global__ __launch_bounds__(256, 2)
void tc_pv(const float* __restrict__ P, const float* __restrict__ v,
           float* __restrict__ attn)
{
    int z = blockIdx.z, b = z >> 4, h = z & 15;
    int m0 = blockIdx.y * 128;
    const float* A  = P + (size_t)z * SS * SS + (size_t)m0 * SS;
    const float* Bp = v + (size_t)b * SS * KVD + (size_t)(h >> 2) * HD;
    float* C = attn + (size_t)b * SS * QD + (size_t)h * HD + (size_t)m0 * QD;
    mma_core<false>(A, SS, 128, Bp, KVD, (const float*)0, C, QD, m0 + 128);
}

__global__ __launch_bounds__(256, 2)
void tc_moe(const float* __restrict__ Ab, const float* __restrict__ W,
            float* __restrict__ out,
            const int* __restrict__ offsets, const int* __restrict__ counts, int N, int K)
{
    int e = blockIdx.z;
    int cnt = counts[e];
    int m0 = blockIdx.y * 128;
    if (m0 >= cnt) return;
    int off = offsets[e];
    int n0 = blockIdx.x * 128;
    mma_core<false>(Ab + ((size_t)off + m0) * K, K, cnt - m0,
                    W + (size_t)e * K * N + n0, N, (const float*)0,
                    out + ((size_t)off + m0) * N + n0, N, K);
}

// ---------------- small kernels ------------------------------------------------
__global__ void zero_counts_kernel(int* counts) {
    if (threadIdx.x < NE) counts[threadIdx.x] = 0;
}

__global__ void rmsnorm_kernel(const float* __restrict__ in, const float* __restrict__ w,
                               float* __restrict__ out) {
    int t = blockIdx.x;
    const float* row = in + (size_t)t * HH;
    float ss = 0.f;
    for (int h = threadIdx.x; h < HH; h += 256) { float v = row[h]; ss += v * v; }
    __shared__ float red[256];
    red[threadIdx.x] = ss; __syncthreads();
    for (int s = 128; s > 0; s >>= 1) {
        if (threadIdx.x < s) red[threadIdx.x] += red[threadIdx.x + s];
        __syncthreads();
    }
    float scale = rsqrtf(red[0] / (float)HH + 1e-5f);
    for (int h = threadIdx.x; h < HH; h += 256)
        out[(size_t)t * HH + h] = row[h] * scale * w[h];
}

__global__ void rope_kernel(float* __restrict__ q, int nheads, int total) {
    int idx = blockIdx.x * blockDim.x + threadIdx.x;
    if (idx >= total) return;
    int d = idx & 63;
    int rest = idx >> 6;
    int head = rest % nheads;
    int t = rest / nheads;
    int s = t & (SS - 1);
    float inv = __powf(10000.f, -(float)d / 64.f);
    float ang = (float)s * inv;
    float c, si; __sincosf(ang, &si, &c);
    size_t base = (size_t)t * nheads * HD + (size_t)head * HD + d;
    float x1 = q[base], x2 = q[base + 64];
    q[base]      = x1 * c - x2 * si;
    q[base + 64] = x2 * c + x1 * si;
}

__global__ void softmax_kernel(float* __restrict__ scores) {
    int z = blockIdx.y, m = blockIdx.x;
    float* row = scores + (size_t)z * SS * SS + (size_t)m * SS;
    int n = m + 1;
    const float scale = 0.08838834764831845f; // 1/sqrt(128)
    __shared__ float red[256];
    float mx = -3.4e38f;
    for (int j = threadIdx.x; j < n; j += 256) mx = fmaxf(mx, row[j]);
    red[threadIdx.x] = mx; __syncthreads();
    for (int s = 128; s > 0; s >>= 1) {
        if (threadIdx.x < s) red[threadIdx.x] = fmaxf(red[threadIdx.x], red[threadIdx.x + s]);
        __syncthreads();
    }
    mx = red[0]; __syncthreads();
    float sum = 0.f;
    for (int j = threadIdx.x; j < n; j += 256) {
        float p = expf((row[j] - mx) * scale);
        row[j] = p;
        sum += p;
    }
    red[threadIdx.x] = sum; __syncthreads();
    for (int s = 128; s > 0; s >>= 1) {
        if (threadIdx.x < s) red[threadIdx.x] += red[threadIdx.x + s];
        __syncthreads();
    }
    float inv = 1.f / red[0];
    for (int j = threadIdx.x; j < n; j += 256) row[j] *= inv;
    int bound = ((m >> 7) + 1) << 7;
    for (int j = n + threadIdx.x; j < bound; j += 256) row[j] = 0.f;
}

__global__ void router_kernel(const float* __restrict__ x, const float* __restrict__ rw,
                              int* __restrict__ topi, float* __restrict__ topw,
                              int* __restrict__ counts)
{
    int t = blockIdx.x;
    const float* row = x + (size_t)t * HH;
    float acc[NE] = {};
    for (int h = threadIdx.x; h < HH; h += 256) {
        float v = row[h];
        const float* r = rw + (size_t)h * NE;
        #pragma unroll
        for (int e = 0; e < NE; e++) acc[e] += v * r[e];
    }
    __shared__ float red[256];
    __shared__ float logits[NE];
    for (int e = 0; e < NE; e++) {
        red[threadIdx.x] = acc[e]; __syncthreads();
        for (int s = 128; s > 0; s >>= 1) {
            if (threadIdx.x < s) red[threadIdx.x] += red[threadIdx.x + s];
            __syncthreads();
        }
        if (threadIdx.x == 0) logits[e] = red[0];
        __syncthreads();
    }
    if (threadIdx.x == 0) {
        float mx = logits[0];
        for (int e = 1; e < NE; e++) mx = fmaxf(mx, logits[e]);
        float p[NE];
        for (int e = 0; e < NE; e++) p[e] = expf(logits[e] - mx);
        int i1 = 0;
        for (int e = 1; e < NE; e++) if (p[e] > p[i1]) i1 = e;
        int i2 = (i1 == 0) ? 1 : 0;
        for (int e = 0; e < NE; e++) if (e != i1 && p[e] > p[i2]) i2 = e;
        float w1 = p[i1], w2 = p[i2];
        float inv = 1.f / (w1 + w2);
        topi[t * 2] = i1;  topi[t * 2 + 1] = i2;
        topw[t * 2] = w1 * inv;  topw[t * 2 + 1] = w2 * inv;
        atomicAdd(&counts[i1], 1);
        atomicAdd(&counts[i2], 1);
    }
}

__global__ void scan_kernel(const int* __restrict__ counts, int* __restrict__ offsets,
                            int* __restrict__ cursor) {
    if (threadIdx.x == 0) {
        int o = 0;
        for (int e = 0; e < NE; e++) { offsets[e] = o; cursor[e] = o; o += counts[e]; }
    }
}

__global__ void scatter_kernel(const int* __restrict__ topi, int* __restrict__ cursor,
                               int* __restrict__ tok, int* __restrict__ slot) {
    int t = blockIdx.x * blockDim.x + threadIdx.x;
    if (t >= TT) return;
    for (int j = 0; j < 2; j++) {
        int e = topi[t * 2 + j];
        int s = atomicAdd(&cursor[e], 1);
        tok[s] = t;
        slot[t * 2 + j] = s;
    }
}

__global__ void gather_kernel(const float* __restrict__ x, const int* __restrict__ tok,
                              float* __restrict__ xg) {
    size_t idx = (size_t)blockIdx.x * blockDim.x + threadIdx.x;
    int slot = (int)(idx >> 11);
    int h = (int)(idx & (HH - 1));
    xg[idx] = x[(size_t)tok[slot] * HH + h];
}

__global__ void silu_mul_kernel(const float* __restrict__ g, const float* __restrict__ u,
                                float* __restrict__ act) {
    size_t idx = (size_t)blockIdx.x * blockDim.x + threadIdx.x;
    float gv = g[idx], uv = u[idx];
    act[idx] = gv / (1.f + expf(-gv)) * uv;
}

__global__ void combine_kernel(const float* __restrict__ hid2, const float* __restrict__ y,
                               const int* __restrict__ slot, const float* __restrict__ topw,
                               float* __restrict__ out)
{
    size_t idx = (size_t)blockIdx.x * blockDim.x + threadIdx.x;
    int t = (int)(idx >> 11);
    int h = (int)(idx & (HH - 1));
    int s0 = slot[t * 2], s1 = slot[t * 2 + 1];
    float w0 = topw[t * 2], w1 = topw[t * 2 + 1];
    out[idx] = hid2[idx] + w0 * y[(size_t)s0 * HH + h] + w1 * y[(size_t)s1 * HH + h];
}

// ---------------- launch -------------------------------------------------------
extern "C" void kernel_launch(void* const* d_in, const int* in_sizes, int n_in,
                              void* d_out, int out_size)
{
    const float* hs  = (const float*)d_in[0];
    const float* ln1 = (const float*)d_in[1];
    const float* ln2 = (const float*)d_in[2];
    const float* wq  = (const float*)d_in[3];
    const float* wk  = (const float*)d_in[4];
    const float* wv  = (const float*)d_in[5];
    const float* wo  = (const float*)d_in[6];
    const float* rw  = (const float*)d_in[7];
    const float* gw  = (const float*)d_in[8];
    const float* uw  = (const float*)d_in[9];
    const float* dw  = (const float*)d_in[10];
    float* out = (float*)d_out;

    float *px, *pq, *pk, *pv, *pscores, *pattn, *phid2, *pxg, *pg, *pu, *py, *ptopw;
    int *ptopi, *pcounts, *poffsets, *pcursor, *ptok, *pslot;
    cudaGetSymbolAddress((void**)&px, g_x);
    cudaGetSymbolAddress((void**)&pq, g_q);
    cudaGetSymbolAddress((void**)&pk, g_k);
    cudaGetSymbolAddress((void**)&pv, g_v);
    cudaGetSymbolAddress((void**)&pscores, g_scores);
    cudaGetSymbolAddress((void**)&pattn, g_attn);
    cudaGetSymbolAddress((void**)&phid2, g_hid2);
    cudaGetSymbolAddress((void**)&pxg, g_xg);
    cudaGetSymbolAddress((void**)&pg, g_g);
    cudaGetSymbolAddress((void**)&pu, g_u);
    cudaGetSymbolAddress((void**)&py, g_y);
    cudaGetSymbolAddress((void**)&ptopi, g_topi);
    cudaGetSymbolAddress((void**)&ptopw, g_topw);
    cudaGetSymbolAddress((void**)&pcounts, g_counts);
    cudaGetSymbolAddress((void**)&poffsets, g_offsets);
    cudaGetSymbolAddress((void**)&pcursor, g_cursor);
    cudaGetSymbolAddress((void**)&ptok, g_tok);
    cudaGetSymbolAddress((void**)&pslot, g_slot);

    cudaFuncSetAttribute(tc_gemm_nn, cudaFuncAttributeMaxDynamicSharedMemorySize, TC_SMEM_BYTES);
    cudaFuncSetAttribute(tc_scores,  cudaFuncAttributeMaxDynamicSharedMemorySize, TC_SMEM_BYTES);
    cudaFuncSetAttribute(tc_pv,      cudaFuncAttributeMaxDynamicSharedMemorySize, TC_SMEM_BYTES);
    cudaFuncSetAttribute(tc_moe,     cudaFuncAttributeMaxDynamicSharedMemorySize, TC_SMEM_BYTES);

    zero_counts_kernel<<<1, 32>>>(pcounts);
    rmsnorm_kernel<<<TT, 256>>>(hs, ln1, px);

    tc_gemm_nn<<<dim3(QD/128,  TT/128), 256, TC_SMEM_BYTES>>>(px, wq, nullptr, pq, TT, QD,  HH);
    tc_gemm_nn<<<dim3(KVD/128, TT/128), 256, TC_SMEM_BYTES>>>(px, wk, nullptr, pk, TT, KVD, HH);
    tc_gemm_nn<<<dim3(KVD/128, TT/128), 256, TC_SMEM_BYTES>>>(px, wv, nullptr, pv, TT, KVD, HH);

    rope_kernel<<<(TT*NH*64)/256, 256>>>(pq, NH, TT*NH*64);
    rope_kernel<<<(TT*NKV*64)/256, 256>>>(pk, NKV, TT*NKV*64);

    tc_scores<<<dim3(SS/128, SS/128, BB*NH), 256, TC_SMEM_BYTES>>>(pq, pk, pscores);
    softmax_kernel<<<dim3(SS, BB*NH), 256>>>(pscores);
    tc_pv<<<dim3(1, SS/128, BB*NH), 256, TC_SMEM_BYTES>>>(pscores, pv, pattn);

    tc_gemm_nn<<<dim3(HH/128, TT/128), 256, TC_SMEM_BYTES>>>(pattn, wo, hs, phid2, TT, HH, QD);

    rmsnorm_kernel<<<TT, 256>>>(phid2, ln2, px);
    router_kernel<<<TT, 256>>>(px, rw, ptopi, ptopw, pcounts);
    scan_kernel<<<1, 32>>>(pcounts, poffsets, pcursor);
    scatter_kernel<<<TT/256, 256>>>(ptopi, pcursor, ptok, pslot);
    gather_kernel<<<(int)(((size_t)NSLOTS*HH)/256), 256>>>(px, ptok, pxg);

    tc_moe<<<dim3(II/128, NSLOTS/128, NE), 256, TC_SMEM_BYTES>>>(pxg, gw, pg, poffsets, pcounts, II, HH);
    tc_moe<<<dim3(II/128, NSLOTS/128, NE), 256, TC_SMEM_BYTES>>>(pxg, uw, pu, poffsets, pcounts, II, HH);
    silu_mul_kernel<<<(int)(((size_t)NSLOTS*II)/256), 256>>>(pg, pu, pg);
    tc_moe<<<dim3(HH/128, NSLOTS/128, NE), 256, TC_SMEM_BYTES>>>(pg, dw, py, poffsets, pcounts, HH, II);

    combine_kernel<<<(int)(((size_t)TT*HH)/256), 256>>>(phid2, py, pslot, ptopw, out);
}

// round 12
// speedup vs baseline: 3.0736x; 1.2180x over previous
#include <cuda_runtime.h>
#include <cuda_bf16.h>
#include <math.h>
#include <cstdint>

// Problem constants
#define BB 2
#define SS 2048
#define HH 2048
#define NH 16
#define NKV 4
#define HD 128
#define NE 8
#define II 4096
#define TT (BB*SS)          // 4096 tokens
#define QD (NH*HD)          // 2048
#define KVD (NKV*HD)        // 512
#define NSLOTS (TT*2)       // 8192 expert assignments

// GEMM pipeline config
#define NSTAGE 4
#define AST 20              // A/directB smem row stride (floats): banks distinct
#define TRS 136             // transB smem k-row stride (floats): 136 % 32 == 8 -> conflict-free frags
#define BSTF 2560           // floats per operand per stage (128*20; transB 16*136=2176 fits)
#define TC_SMEM_BYTES (NSTAGE * 2 * BSTF * 4)   // 81920 bytes

// ---------------- static scratch ----------------------------------------------
__device__ float g_x[(size_t)TT*HH];
__device__ float g_q[(size_t)TT*QD];
__device__ float g_k[(size_t)TT*KVD];
__device__ float g_v[(size_t)TT*KVD];
__device__ float g_scores[(size_t)BB*NH*SS*SS];
__device__ float g_attn[(size_t)TT*QD];
__device__ float g_hid2[(size_t)TT*HH];
__device__ float g_xg[(size_t)NSLOTS*HH];
__device__ float g_g[(size_t)NSLOTS*II];
__device__ float g_u[(size_t)NSLOTS*II];
__device__ float g_y[(size_t)NSLOTS*HH];
__device__ int   g_topi[NSLOTS];
__device__ float g_topw[NSLOTS];
__device__ int   g_counts[NE];
__device__ int   g_offsets[NE];
__device__ int   g_cursor[NE];
__device__ int   g_tok[NSLOTS];
__device__ int   g_slot[NSLOTS];

// ---------------- helpers -------------------------------------------------------
__device__ __forceinline__ uint32_t smem_u32(const void* p) {
    uint32_t a;
    asm("{ .reg .u64 t; cvta.to.shared.u64 t, %1; cvt.u32.u64 %0, t; }" : "=r"(a) : "l"(p));
    return a;
}
__device__ __forceinline__ float to_tf32(float x) {
    float r; asm("cvt.rna.tf32.f32 %0, %1;" : "=f"(r) : "f"(x)); return r;
}
__device__ __forceinline__ uint32_t frag(const float* p) {
    return __float_as_uint(to_tf32(*p));
}
__device__ __forceinline__ void mma_tf32(float* d, const uint32_t* a, const uint32_t* b) {
    asm volatile(
        "mma.sync.aligned.m16n8k8.row.col.f32.tf32.tf32.f32 "
        "{%0,%1,%2,%3}, {%4,%5,%6,%7}, {%8,%9}, {%0,%1,%2,%3};"
        : "+f"(d[0]), "+f"(d[1]), "+f"(d[2]), "+f"(d[3])
        : "r"(a[0]), "r"(a[1]), "r"(a[2]), "r"(a[3]), "r"(b[0]), "r"(b[1]));
}
__device__ __forceinline__ void cp16(uint32_t s, const void* g, int sz) {
    asm volatile("cp.async.cg.shared.global [%0], [%1], 16, %2;"
                 :: "r"(s), "l"(g), "r"(sz) : "memory");
}
#define CP_COMMIT() asm volatile("cp.async.commit_group;" ::: "memory")
#define CP_WAIT(N)  asm volatile("cp.async.wait_group %0;" :: "n"(N) : "memory")

// ---------------- tf32 MMA GEMM core: 128x128 CTA tile, BK=16, 4-stage cp.async --
// BDIRECT=true : B is [N,K] row-major (K contiguous), stride ldb.
// BDIRECT=false: B is [K,N] row-major (N contiguous), stride ldb.
template<bool BDIRECT>
__device__ __forceinline__ void mma_core(
    const float* __restrict__ A, int lda, int Mrem,
    const float* __restrict__ B, int ldb,
    const float* __restrict__ D, float* __restrict__ C, int ldc, int K)
{
    extern __shared__ __align__(16) float smemf[];
    uint32_t sbase = smem_u32(smemf);
    int tid = threadIdx.x;
    int wid = tid >> 5;
    int lane = tid & 31;

    // loader mapping (A / direct-B): row r, float offset ako (0 or 8), 2x cp16
    int ar  = tid >> 1;
    int ako = (tid & 1) * 8;
    // trans-B loader mapping: k row, n offset, 2x cp16
    int bk = tid >> 4;          // 0..15
    int bn = (tid & 15) * 8;    // 0..120

    // compute mapping: warp (wid>>2, wid&3) -> 64x32 region
    int wm = (wid >> 2) * 64;
    int wn = (wid & 3) * 32;
    int qrow = lane >> 2;       // 0..7
    int kq = lane & 3;          // 0..3

    float acc[4][4][4];
    #pragma unroll
    for (int i = 0; i < 4; i++)
        #pragma unroll
        for (int j = 0; j < 4; j++)
            #pragma unroll
            for (int c = 0; c < 4; c++) acc[i][j][c] = 0.f;

    int KT = K >> 4;            // chunks of 16

    int a_sz = (ar < Mrem) ? 16 : 0;
    const float* agbase = A + (size_t)ar * lda + ako;
    uint32_t a_soff = (uint32_t)(ar * AST + ako) * 4;
    uint32_t b_soff_d = a_soff;
    const float* bgbase_d = BDIRECT ? (B + (size_t)ar * ldb + ako) : (const float*)0;
    const float* bgbase_t = BDIRECT ? (const float*)0 : (B + (size_t)bk * ldb + bn);
    uint32_t b_soff_t = (uint32_t)(bk * TRS + bn) * 4;

    // prologue: issue stages 0..NSTAGE-2
    #pragma unroll
    for (int c = 0; c < NSTAGE - 1; c++) {
        int s = c;
        int kc = c << 4;
        uint32_t ab = sbase + (uint32_t)s * (BSTF * 4);
        uint32_t bb = sbase + (uint32_t)(NSTAGE + s) * (BSTF * 4);
        cp16(ab + a_soff,      agbase + kc,     a_sz);
        cp16(ab + a_soff + 16, agbase + kc + 4, a_sz);
        if (BDIRECT) {
            cp16(bb + b_soff_d,      bgbase_d + kc,     16);
            cp16(bb + b_soff_d + 16, bgbase_d + kc + 4, 16);
        } else {
            cp16(bb + b_soff_t,      bgbase_t + (size_t)kc * ldb,     16);
            cp16(bb + b_soff_t + 16, bgbase_t + (size_t)kc * ldb + 4, 16);
        }
        CP_COMMIT();
    }

    for (int kt = 0; kt < KT; kt++) {
        CP_WAIT(NSTAGE - 2);
        __syncthreads();

        // issue chunk kt+NSTAGE-1 into recycled buffer
        int nc = kt + NSTAGE - 1;
        if (nc < KT) {
            int s = nc & (NSTAGE - 1);
            int kc = nc << 4;
            uint32_t ab = sbase + (uint32_t)s * (BSTF * 4);
            uint32_t bb = sbase + (uint32_t)(NSTAGE + s) * (BSTF * 4);
            cp16(ab + a_soff,      agbase + kc,     a_sz);
            cp16(ab + a_soff + 16, agbase + kc + 4, a_sz);
            if (BDIRECT) {
                cp16(bb + b_soff_d,      bgbase_d + kc,     16);
                cp16(bb + b_soff_d + 16, bgbase_d + kc + 4, 16);
            } else {
                cp16(bb + b_soff_t,      bgbase_t + (size_t)kc * ldb,     16);
                cp16(bb + b_soff_t + 16, bgbase_t + (size_t)kc * ldb + 4, 16);
            }
        }
        CP_COMMIT();

        // compute on stage kt % NSTAGE (2 k8 steps)
        int s = kt & (NSTAGE - 1);
        const float* As = smemf + (size_t)s * BSTF;
        const float* Bs = smemf + (size_t)(NSTAGE + s) * BSTF;
        #pragma unroll
        for (int kk = 0; kk < 2; kk++) {
            int kb = kk * 8 + kq;
            uint32_t afr[4][4], bfr[4][2];
            #pragma unroll
            for (int mt = 0; mt < 4; mt++) {
                const float* ab = As + (wm + mt*16 + qrow) * AST + kb;
                afr[mt][0] = frag(ab);
                afr[mt][1] = frag(ab + 8*AST);
                afr[mt][2] = frag(ab + 4);
                afr[mt][3] = frag(ab + 8*AST + 4);
            }
            #pragma unroll
            for (int nt = 0; nt < 4; nt++) {
                if (BDIRECT) {
                    const float* bb = Bs + (wn + nt*8 + qrow) * AST + kb;
                    bfr[nt][0] = frag(bb);
                    bfr[nt][1] = frag(bb + 4);
                } else {
                    const float* bb = Bs + (size_t)kb * TRS + wn + nt*8 + qrow;
                    bfr[nt][0] = frag(bb);
                    bfr[nt][1] = frag(bb + 4*TRS);
                }
            }
            #pragma unroll
            for (int mt = 0; mt < 4; mt++)
                #pragma unroll
                for (int nt = 0; nt < 4; nt++)
                    mma_tf32(acc[mt][nt], afr[mt], bfr[nt]);
        }
    }

    // ---- epilogue ----
    #pragma unroll
    for (int mt = 0; mt < 4; mt++) {
        int r0 = wm + mt*16 + qrow;
        #pragma unroll
        for (int nt = 0; nt < 4; nt++) {
            int c0 = wn + nt*8 + kq*2;
            if (r0 < Mrem) {
                float2 v = make_float2(acc[mt][nt][0], acc[mt][nt][1]);
                if (D) {
                    float2 d = *(const float2*)(D + (size_t)r0 * ldc + c0);
                    v.x += d.x; v.y += d.y;
                }
                *(float2*)(C + (size_t)r0 * ldc + c0) = v;
            }
            int r1 = r0 + 8;
            if (r1 < Mrem) {
                float2 v = make_float2(acc[mt][nt][2], acc[mt][nt][3]);
                if (D) {
                    float2 d = *(const float2*)(D + (size_t)r1 * ldc + c0);
                    v.x += d.x; v.y += d.y;
                }
                *(float2*)(C + (size_t)r1 * ldc + c0) = v;
            }
        }
    }
}

// ---------------- GEMM wrappers ------------------------------------------------
__global__ __launch_bounds__(256, 2)
void tc_gemm_nn(const float* __restrict__ A, const float* __restrict__ B,
                const float* __restrict__ D, float* __restrict__ C, int M, int N, int K)
{
    int m0 = blockIdx.y * 128, n0 = blockIdx.x * 128;
    mma_core<false>(A + (size_t)m0 * K, K, M - m0,
                    B + n0, N,
                    D ? D + (size_t)m0 * N + n0 : (const float*)0,
                    C + (size_t)m0 * N + n0, N, K);
}

__global__ __launch_bounds__(256, 2)
void tc_scores(const float* __restrict__ q, const float* __restrict__ k,
               float* __restrict__ scores)
{
    int z = blockIdx.z, b = z >> 4, h = z & 15;
    int m0 = blockIdx.y * 128, n0 = blockIdx.x * 128;
    if (n0 >= m0 + 128) return;  // causal skip
    const float* A  = q + (size_t)b * SS * QD + (size_t)h * HD + (size_t)m0 * QD;
    const float* Bp = k + (size_t)b * SS * KVD + (size_t)(h >> 2) * HD + (size_t)n0 * KVD;
    float* C = scores + (size_t)z * SS * SS + (size_t)m0 * SS + n0;
    mma_core<true>(A, QD, 128, Bp, KVD, (const float*)0, C, SS, HD);
}

__global__ __launch_bounds__(256, 2)
void tc_pv(const float* __restrict__ P, const float* __restrict__ v,
           float* __restrict__ attn)
{
    int z = blockIdx.z, b = z >> 4, h = z & 15;
    int m0 = blockIdx.y * 128;
    const float* A  = P + (size_t)z * SS * SS + (size_t)m0 * SS;
    const float* Bp = v + (size_t)b * SS * KVD + (size_t)(h >> 2) * HD;
    float* C = attn + (size_t)b * SS * QD + (size_t)h * HD + (size_t)m0 * QD;
    mma_core<false>(A, SS, 128, Bp, KVD, (const float*)0, C, QD, m0 + 128);
}

__global__ __launch_bounds__(256, 2)
void tc_moe(const float* __restrict__ Ab, const float* __restrict__ W,
            float* __restrict__ out,
            const int* __restrict__ offsets, const int* __restrict__ counts, int N, int K)
{
    int e = blockIdx.z;
    int cnt = counts[e];
    int m0 = blockIdx.y * 128;
    if (m0 >= cnt) return;
    int off = offsets[e];
    int n0 = blockIdx.x * 128;
    mma_core<false>(Ab + ((size_t)off + m0) * K, K, cnt - m0,
                    W + (size_t)e * K * N + n0, N, (const float*)0,
                    out + ((size_t)off + m0) * N + n0, N, K);
}

// ---------------- small kernels ------------------------------------------------
__global__ void zero_counts_kernel(int* counts) {
    if (threadIdx.x < NE) counts[threadIdx.x] = 0;
}

__global__ void rmsnorm_kernel(const float* __restrict__ in, const float* __restrict__ w,
                               float* __restrict__ out) {
    int t = blockIdx.x;
    const float* row = in + (size_t)t * HH;
    float ss = 0.f;
    for (int h = threadIdx.x; h < HH; h += 256) { float v = row[h]; ss += v * v; }
    __shared__ float red[256];
    red[threadIdx.x] = ss; __syncthreads();
    for (int s = 128; s > 0; s >>= 1) {
        if (threadIdx.x < s) red[threadIdx.x] += red[threadIdx.x + s];
        __syncthreads();
    }
    float scale = rsqrtf(red[0] / (float)HH + 1e-5f);
    for (int h = threadIdx.x; h < HH; h += 256)
        out[(size_t)t * HH + h] = row[h] * scale * w[h];
}

__global__ void rope_kernel(float* __restrict__ q, int nheads, int total) {
    int idx = blockIdx.x * blockDim.x + threadIdx.x;
    if (idx >= total) return;
    int d = idx & 63;
    int rest = idx >> 6;
    int head = rest % nheads;
    int t = rest / nheads;
    int s = t & (SS - 1);
    float inv = __powf(10000.f, -(float)d / 64.f);
    float ang = (float)s * inv;
    float c, si; __sincosf(ang, &si, &c);
    size_t base = (size_t)t * nheads * HD + (size_t)head * HD + d;
    float x1 = q[base], x2 = q[base + 64];
    q[base]      = x1 * c - x2 * si;
    q[base + 64] = x2 * c + x1 * si;
}

__global__ void softmax_kernel(float* __restrict__ scores) {
    int z = blockIdx.y, m = blockIdx.x;
    float* row = scores + (size_t)z * SS * SS + (size_t)m * SS;
    int n = m + 1;
    const float scale = 0.08838834764831845f; // 1/sqrt(128)
    __shared__ float red[256];
    float mx = -3.4e38f;
    for (int j = threadIdx.x; j < n; j += 256) mx = fmaxf(mx, row[j]);
    red[threadIdx.x] = mx; __syncthreads();
    for (int s = 128; s > 0; s >>= 1) {
        if (threadIdx.x < s) red[threadIdx.x] = fmaxf(red[threadIdx.x], red[threadIdx.x + s]);
        __syncthreads();
    }
    mx = red[0]; __syncthreads();
    float sum = 0.f;
    for (int j = threadIdx.x; j < n; j += 256) {
        float p = expf((row[j] - mx) * scale);
        row[j] = p;
        sum += p;
    }
    red[threadIdx.x] = sum; __syncthreads();
    for (int s = 128; s > 0; s >>= 1) {
        if (threadIdx.x < s) red[threadIdx.x] += red[threadIdx.x + s];
        __syncthreads();
    }
    float inv = 1.f / red[0];
    for (int j = threadIdx.x; j < n; j += 256) row[j] *= inv;
    int bound = ((m >> 7) + 1) << 7;
    for (int j = n + threadIdx.x; j < bound; j += 256) row[j] = 0.f;
}

__global__ void router_kernel(const float* __restrict__ x, const float* __restrict__ rw,
                              int* __restrict__ topi, float* __restrict__ topw,
                              int* __restrict__ counts)
{
    int t = blockIdx.x;
    const float* row = x + (size_t)t * HH;
    float acc[NE] = {};
    for (int h = threadIdx.x; h < HH; h += 256) {
        float v = row[h];
        const float* r = rw + (size_t)h * NE;
        #pragma unroll
        for (int e = 0; e < NE; e++) acc[e] += v * r[e];
    }
    __shared__ float red[256];
    __shared__ float logits[NE];
    for (int e = 0; e < NE; e++) {
        red[threadIdx.x] = acc[e]; __syncthreads();
        for (int s = 128; s > 0; s >>= 1) {
            if (threadIdx.x < s) red[threadIdx.x] += red[threadIdx.x + s];
            __syncthreads();
        }
        if (threadIdx.x == 0) logits[e] = red[0];
        __syncthreads();
    }
    if (threadIdx.x == 0) {
        float mx = logits[0];
        for (int e = 1; e < NE; e++) mx = fmaxf(mx, logits[e]);
        float p[NE];
        for (int e = 0; e < NE; e++) p[e] = expf(logits[e] - mx);
        int i1 = 0;
        for (int e = 1; e < NE; e++) if (p[e] > p[i1]) i1 = e;
        int i2 = (i1 == 0) ? 1 : 0;
        for (int e = 0; e < NE; e++) if (e != i1 && p[e] > p[i2]) i2 = e;
        float w1 = p[i1], w2 = p[i2];
        float inv = 1.f / (w1 + w2);
        topi[t * 2] = i1;  topi[t * 2 + 1] = i2;
        topw[t * 2] = w1 * inv;  topw[t * 2 + 1] = w2 * inv;
        atomicAdd(&counts[i1], 1);
        atomicAdd(&counts[i2], 1);
    }
}

__global__ void scan_kernel(const int* __restrict__ counts, int* __restrict__ offsets,
                            int* __restrict__ cursor) {
    if (threadIdx.x == 0) {
        int o = 0;
        for (int e = 0; e < NE; e++) { offsets[e] = o; cursor[e] = o; o += counts[e]; }
    }
}

__global__ void scatter_kernel(const int* __restrict__ topi, int* __restrict__ cursor,
                               int* __restrict__ tok, int* __restrict__ slot) {
    int t = blockIdx.x * blockDim.x + threadIdx.x;
    if (t >= TT) return;
    for (int j = 0; j < 2; j++) {
        int e = topi[t * 2 + j];
        int s = atomicAdd(&cursor[e], 1);
        tok[s] = t;
        slot[t * 2 + j] = s;
    }
}

__global__ void gather_kernel(const float* __restrict__ x, const int* __restrict__ tok,
                              float* __restrict__ xg) {
    size_t idx = (size_t)blockIdx.x * blockDim.x + threadIdx.x;
    int slot = (int)(idx >> 11);
    int h = (int)(idx & (HH - 1));
    xg[idx] = x[(size_t)tok[slot] * HH + h];
}

__global__ void silu_mul_kernel(const float* __restrict__ g, const float* __restrict__ u,
                                float* __restrict__ act) {
    size_t idx = (size_t)blockIdx.x * blockDim.x + threadIdx.x;
    float gv = g[idx], uv = u[idx];
    act[idx] = gv / (1.f + expf(-gv)) * uv;
}

__global__ void combine_kernel(const float* __restrict__ hid2, const float* __restrict__ y,
                               const int* __restrict__ slot, const float* __restrict__ topw,
                               float* __restrict__ out)
{
    size_t idx = (size_t)blockIdx.x * blockDim.x + threadIdx.x;
    int t = (int)(idx >> 11);
    int h = (int)(idx & (HH - 1));
    int s0 = slot[t * 2], s1 = slot[t * 2 + 1];
    float w0 = topw[t * 2], w1 = topw[t * 2 + 1];
    out[idx] = hid2[idx] + w0 * y[(size_t)s0 * HH + h] + w1 * y[(size_t)s1 * HH + h];
}

// ---------------- launch -------------------------------------------------------
extern "C" void kernel_launch(void* const* d_in, const int* in_sizes, int n_in,
                              void* d_out, int out_size)
{
    const float* hs  = (const float*)d_in[0];
    const float* ln1 = (const float*)d_in[1];
    const float* ln2 = (const float*)d_in[2];
    const float* wq  = (const float*)d_in[3];
    const float* wk  = (const float*)d_in[4];
    const float* wv  = (const float*)d_in[5];
    const float* wo  = (const float*)d_in[6];
    const float* rw  = (const float*)d_in[7];
    const float* gw  = (const float*)d_in[8];
    const float* uw  = (const float*)d_in[9];
    const float* dw  = (const float*)d_in[10];
    float* out = (float*)d_out;

    float *px, *pq, *pk, *pv, *pscores, *pattn, *phid2, *pxg, *pg, *pu, *py, *ptopw;
    int *ptopi, *pcounts, *poffsets, *pcursor, *ptok, *pslot;
    cudaGetSymbolAddress((void**)&px, g_x);
    cudaGetSymbolAddress((void**)&pq, g_q);
    cudaGetSymbolAddress((void**)&pk, g_k);
    cudaGetSymbolAddress((void**)&pv, g_v);
    cudaGetSymbolAddress((void**)&pscores, g_scores);
    cudaGetSymbolAddress((void**)&pattn, g_attn);
    cudaGetSymbolAddress((void**)&phid2, g_hid2);
    cudaGetSymbolAddress((void**)&pxg, g_xg);
    cudaGetSymbolAddress((void**)&pg, g_g);
    cudaGetSymbolAddress((void**)&pu, g_u);
    cudaGetSymbolAddress((void**)&py, g_y);
    cudaGetSymbolAddress((void**)&ptopi, g_topi);
    cudaGetSymbolAddress((void**)&ptopw, g_topw);
    cudaGetSymbolAddress((void**)&pcounts, g_counts);
    cudaGetSymbolAddress((void**)&poffsets, g_offsets);
    cudaGetSymbolAddress((void**)&pcursor, g_cursor);
    cudaGetSymbolAddress((void**)&ptok, g_tok);
    cudaGetSymbolAddress((void**)&pslot, g_slot);

    cudaFuncSetAttribute(tc_gemm_nn, cudaFuncAttributeMaxDynamicSharedMemorySize, TC_SMEM_BYTES);
    cudaFuncSetAttribute(tc_scores,  cudaFuncAttributeMaxDynamicSharedMemorySize, TC_SMEM_BYTES);
    cudaFuncSetAttribute(tc_pv,      cudaFuncAttributeMaxDynamicSharedMemorySize, TC_SMEM_BYTES);
    cudaFuncSetAttribute(tc_moe,     cudaFuncAttributeMaxDynamicSharedMemorySize, TC_SMEM_BYTES);

    zero_counts_kernel<<<1, 32>>>(pcounts);
    rmsnorm_kernel<<<TT, 256>>>(hs, ln1, px);

    tc_gemm_nn<<<dim3(QD/128,  TT/128), 256, TC_SMEM_BYTES>>>(px, wq, nullptr, pq, TT, QD,  HH);
    tc_gemm_nn<<<dim3(KVD/128, TT/128), 256, TC_SMEM_BYTES>>>(px, wk, nullptr, pk, TT, KVD, HH);
    tc_gemm_nn<<<dim3(KVD/128, TT/128), 256, TC_SMEM_BYTES>>>(px, wv, nullptr, pv, TT, KVD, HH);

    rope_kernel<<<(TT*NH*64)/256, 256>>>(pq, NH, TT*NH*64);
    rope_kernel<<<(TT*NKV*64)/256, 256>>>(pk, NKV, TT*NKV*64);

    tc_scores<<<dim3(SS/128, SS/128, BB*NH), 256, TC_SMEM_BYTES>>>(pq, pk, pscores);
    softmax_kernel<<<dim3(SS, BB*NH), 256>>>(pscores);
    tc_pv<<<dim3(1, SS/128, BB*NH), 256, TC_SMEM_BYTES>>>(pscores, pv, pattn);

    tc_gemm_nn<<<dim3(HH/128, TT/128), 256, TC_SMEM_BYTES>>>(pattn, wo, hs, phid2, TT, HH, QD);

    rmsnorm_kernel<<<TT, 256>>>(phid2, ln2, px);
    router_kernel<<<TT, 256>>>(px, rw, ptopi, ptopw, pcounts);
    scan_kernel<<<1, 32>>>(pcounts, poffsets, pcursor);
    scatter_kernel<<<TT/256, 256>>>(ptopi, pcursor, ptok, pslot);
    gather_kernel<<<(int)(((size_t)NSLOTS*HH)/256), 256>>>(px, ptok, pxg);

    tc_moe<<<dim3(II/128, NSLOTS/128, NE), 256, TC_SMEM_BYTES>>>(pxg, gw, pg, poffsets, pcounts, II, HH);
    tc_moe<<<dim3(II/128, NSLOTS/128, NE), 256, TC_SMEM_BYTES>>>(pxg, uw, pu, poffsets, pcounts, II, HH);
    silu_mul_kernel<<<(int)(((size_t)NSLOTS*II)/256), 256>>>(pg, pu, pg);
    tc_moe<<<dim3(HH/128, NSLOTS/128, NE), 256, TC_SMEM_BYTES>>>(pg, dw, py, poffsets, pcounts, HH, II);

    combine_kernel<<<(int)(((size_t)TT*HH)/256), 256>>>(phid2, py, pslot, ptopw, out);
}

// round 14
// speedup vs baseline: 4.7032x; 1.5302x over previous
#include <cuda_runtime.h>
#include <cuda_bf16.h>
#include <math.h>
#include <cstdint>

// Problem constants
#define BB 2
#define SS 2048
#define HH 2048
#define NH 16
#define NKV 4
#define HD 128
#define NE 8
#define II 4096
#define TT (BB*SS)          // 4096 tokens
#define QD (NH*HD)          // 2048
#define KVD (NKV*HD)        // 512
#define NSLOTS (TT*2)       // 8192 expert assignments

// GEMM pipeline config: BK=16, dense rows of 16 floats
#define NSTAGE 4
#define BSTG 2048                      // floats per operand per stage (128*16)
#define TC_SMEM_BYTES (NSTAGE * 2 * BSTG * 4)   // 65536 bytes

// ---------------- static scratch ----------------------------------------------
__device__ float g_x[(size_t)TT*HH];
__device__ float g_q[(size_t)TT*QD];
__device__ float g_k[(size_t)TT*KVD];
__device__ float g_v[(size_t)TT*KVD];
__device__ float g_scores[(size_t)BB*NH*SS*SS];
__device__ float g_attn[(size_t)TT*QD];
__device__ float g_hid2[(size_t)TT*HH];
__device__ float g_xg[(size_t)NSLOTS*HH];
__device__ float g_g[(size_t)NSLOTS*II];
__device__ float g_u[(size_t)NSLOTS*II];
__device__ float g_y[(size_t)NSLOTS*HH];
__device__ int   g_topi[NSLOTS];
__device__ float g_topw[NSLOTS];
__device__ int   g_counts[NE];
__device__ int   g_offsets[NE];
__device__ int   g_cursor[NE];
__device__ int   g_tok[NSLOTS];
__device__ int   g_slot[NSLOTS];
// transposed (and tf32-prerounded) operands
__device__ float g_wqT[(size_t)QD*HH];          // 16MB
__device__ float g_wkT[(size_t)KVD*HH];         // 4MB
__device__ float g_wvT[(size_t)KVD*HH];         // 4MB
__device__ float g_woT[(size_t)HH*QD];          // 16MB
__device__ float g_gwT[(size_t)NE*II*HH];       // 256MB
__device__ float g_uwT[(size_t)NE*II*HH];       // 256MB
__device__ float g_dwT[(size_t)NE*HH*II];       // 256MB
__device__ float g_vT[(size_t)BB*NKV*HD*SS];    // 8MB

// ---------------- helpers -------------------------------------------------------
__device__ __forceinline__ uint32_t smem_u32(const void* p) {
    uint32_t a;
    asm("{ .reg .u64 t; cvta.to.shared.u64 t, %1; cvt.u32.u64 %0, t; }" : "=r"(a) : "l"(p));
    return a;
}
__device__ __forceinline__ float to_tf32(float x) {
    float r; asm("cvt.rna.tf32.f32 %0, %1;" : "=f"(r) : "f"(x)); return r;
}
__device__ __forceinline__ void mma_tf32(float* d, const uint32_t* a, const uint32_t* b) {
    asm volatile(
        "mma.sync.aligned.m16n8k8.row.col.f32.tf32.tf32.f32 "
        "{%0,%1,%2,%3}, {%4,%5,%6,%7}, {%8,%9}, {%0,%1,%2,%3};"
        : "+f"(d[0]), "+f"(d[1]), "+f"(d[2]), "+f"(d[3])
        : "r"(a[0]), "r"(a[1]), "r"(a[2]), "r"(a[3]), "r"(b[0]), "r"(b[1]));
}
__device__ __forceinline__ void cp16(uint32_t s, const void* g, int sz) {
    asm volatile("cp.async.cg.shared.global [%0], [%1], 16, %2;"
                 :: "r"(s), "l"(g), "r"(sz) : "memory");
}
#define CP_COMMIT() asm volatile("cp.async.commit_group;" ::: "memory")
#define CP_WAIT(N)  asm volatile("cp.async.wait_group %0;" :: "n"(N) : "memory")

// ---------------- tf32 MMA GEMM core ------------------------------------------
// C[128x128] = A[128xK] * B[N=128 rows][K] (both K-contiguous, tf32-prerounded).
// K-permuted fragments: lane kq covers k-cols {4kq..4kq+3}; one LDS.128 feeds
// both k8 steps of a 16-wide stage. ROUND: round C to tf32 on store.
template<bool ROUND>
__device__ __forceinline__ void mma_core(
    const float* __restrict__ A, int lda, int Mrem,
    const float* __restrict__ B, int ldb,
    const float* __restrict__ D, float* __restrict__ C, int ldc, int K)
{
    extern __shared__ __align__(16) float smemf[];
    uint32_t sbase = smem_u32(smemf);
    int tid = threadIdx.x;
    int wid = tid >> 5;
    int lane = tid & 31;

    // loader mapping: row ar (0..127), half ako (0/8): 2 cp16 per operand
    int ar  = tid >> 1;
    int ako = (tid & 1) * 8;
    int a_sz = (ar < Mrem) ? 16 : 0;
    const float* agbase = A + (size_t)ar * lda + ako;
    const float* bgbase = B + (size_t)ar * ldb + ako;
    uint32_t soff = (uint32_t)(ar * 16 + ako) * 4;

    // compute mapping: warp (wid>>2, wid&3) -> 64x32 region
    int wm = (wid >> 2) * 64;
    int wn = (wid & 3) * 32;
    int qrow = lane >> 2;       // 0..7
    int kq4 = (lane & 3) * 4;   // 0,4,8,12

    float acc[4][4][4];
    #pragma unroll
    for (int i = 0; i < 4; i++)
        #pragma unroll
        for (int j = 0; j < 4; j++)
            #pragma unroll
            for (int c = 0; c < 4; c++) acc[i][j][c] = 0.f;

    int KT = K >> 4;

    // prologue: stages 0..NSTAGE-2
    #pragma unroll
    for (int c = 0; c < NSTAGE - 1; c++) {
        int kc = c << 4;
        uint32_t ab = sbase + (uint32_t)c * (BSTG * 4);
        uint32_t bb = sbase + (uint32_t)(NSTAGE + c) * (BSTG * 4);
        cp16(ab + soff,      agbase + kc,     a_sz);
        cp16(ab + soff + 16, agbase + kc + 4, a_sz);
        cp16(bb + soff,      bgbase + kc,     16);
        cp16(bb + soff + 16, bgbase + kc + 4, 16);
        CP_COMMIT();
    }

    for (int kt = 0; kt < KT; kt++) {
        CP_WAIT(NSTAGE - 2);
        __syncthreads();

        int nc = kt + NSTAGE - 1;
        if (nc < KT) {
            int s = nc & (NSTAGE - 1);
            int kc = nc << 4;
            uint32_t ab = sbase + (uint32_t)s * (BSTG * 4);
            uint32_t bb = sbase + (uint32_t)(NSTAGE + s) * (BSTG * 4);
            cp16(ab + soff,      agbase + kc,     a_sz);
            cp16(ab + soff + 16, agbase + kc + 4, a_sz);
            cp16(bb + soff,      bgbase + kc,     16);
            cp16(bb + soff + 16, bgbase + kc + 4, 16);
        }
        CP_COMMIT();

        int s = kt & (NSTAGE - 1);
        const float* As = smemf + (size_t)s * BSTG;
        const float* Bs = smemf + (size_t)(NSTAGE + s) * BSTG;

        float4 av0[4], av1[4], bv[4];
        #pragma unroll
        for (int mt = 0; mt < 4; mt++) {
            const float* ab = As + (wm + mt*16 + qrow) * 16 + kq4;
            av0[mt] = *(const float4*)ab;
            av1[mt] = *(const float4*)(ab + 128);   // row +8
        }
        #pragma unroll
        for (int nt = 0; nt < 4; nt++)
            bv[nt] = *(const float4*)(Bs + (wn + nt*8 + qrow) * 16 + kq4);

        // step 0: cols {4kq, 4kq+1}
        #pragma unroll
        for (int mt = 0; mt < 4; mt++) {
            uint32_t afr[4] = { __float_as_uint(av0[mt].x), __float_as_uint(av1[mt].x),
                                __float_as_uint(av0[mt].y), __float_as_uint(av1[mt].y) };
            #pragma unroll
            for (int nt = 0; nt < 4; nt++) {
                uint32_t bfr[2] = { __float_as_uint(bv[nt].x), __float_as_uint(bv[nt].y) };
                mma_tf32(acc[mt][nt], afr, bfr);
            }
        }
        // step 1: cols {4kq+2, 4kq+3}
        #pragma unroll
        for (int mt = 0; mt < 4; mt++) {
            uint32_t afr[4] = { __float_as_uint(av0[mt].z), __float_as_uint(av1[mt].z),
                                __float_as_uint(av0[mt].w), __float_as_uint(av1[mt].w) };
            #pragma unroll
            for (int nt = 0; nt < 4; nt++) {
                uint32_t bfr[2] = { __float_as_uint(bv[nt].z), __float_as_uint(bv[nt].w) };
                mma_tf32(acc[mt][nt], afr, bfr);
            }
        }
    }

    // ---- epilogue ----
    int kq = lane & 3;
    #pragma unroll
    for (int mt = 0; mt < 4; mt++) {
        int r0 = wm + mt*16 + qrow;
        #pragma unroll
        for (int nt = 0; nt < 4; nt++) {
            int c0 = wn + nt*8 + kq*2;
            if (r0 < Mrem) {
                float2 v = make_float2(acc[mt][nt][0], acc[mt][nt][1]);
                if (D) {
                    float2 d = *(const float2*)(D + (size_t)r0 * ldc + c0);
                    v.x += d.x; v.y += d.y;
                }
                if (ROUND) { v.x = to_tf32(v.x); v.y = to_tf32(v.y); }
                *(float2*)(C + (size_t)r0 * ldc + c0) = v;
            }
            int r1 = r0 + 8;
            if (r1 < Mrem) {
                float2 v = make_float2(acc[mt][nt][2], acc[mt][nt][3]);
                if (D) {
                    float2 d = *(const float2*)(D + (size_t)r1 * ldc + c0);
                    v.x += d.x; v.y += d.y;
                }
                if (ROUND) { v.x = to_tf32(v.x); v.y = to_tf32(v.y); }
                *(float2*)(C + (size_t)r1 * ldc + c0) = v;
            }
        }
    }
}

// ---------------- GEMM wrappers ------------------------------------------------
__global__ __launch_bounds__(256, 2)
void tc_gemm(const float* __restrict__ A, const float* __restrict__ Bt,
             const float* __restrict__ D, float* __restrict__ C, int M, int N, int K)
{
    int m0 = blockIdx.y * 128, n0 = blockIdx.x * 128;
    mma_core<false>(A + (size_t)m0 * K, K, M - m0,
                    Bt + (size_t)n0 * K, K,
                    D ? D + (size_t)m0 * N + n0 : (const float*)0,
                    C + (size_t)m0 * N + n0, N, K);
}

__global__ __launch_bounds__(256, 2)
void tc_scores(const float* __restrict__ q, const float* __restrict__ k,
               float* __restrict__ scores)
{
    int z = blockIdx.z, b = z >> 4, h = z & 15;
    int m0 = blockIdx.y * 128, n0 = blockIdx.x * 128;
    if (n0 >= m0 + 128) return;  // causal skip
    const float* A  = q + (size_t)b * SS * QD + (size_t)h * HD + (size_t)m0 * QD;
    const float* Bp = k + (size_t)b * SS * KVD + (size_t)(h >> 2) * HD + (size_t)n0 * KVD;
    float* C = scores + (size_t)z * SS * SS + (size_t)m0 * SS + n0;
    mma_core<false>(A, QD, 128, Bp, KVD, (const float*)0, C, SS, HD);
}

__global__ __launch_bounds__(256, 2)
void tc_pv(const float* __restrict__ P, const float* __restrict__ vt,
           float* __restrict__ attn)
{
    int z = blockIdx.z, b = z >> 4, h = z & 15;
    int m0 = blockIdx.y * 128;
    const float* A  = P + (size_t)z * SS * SS + (size_t)m0 * SS;
    const float* Bp = vt + ((size_t)(b * NKV + (h >> 2)) * HD) * SS;  // [d][s]
    float* C = attn + (size_t)b * SS * QD + (size_t)h * HD + (size_t)m0 * QD;
    mma_core<true>(A, SS, 128, Bp, SS, (const float*)0, C, QD, m0 + 128);
}

__global__ __launch_bounds__(256, 2)
void tc_moe(const float* __restrict__ Ab, const float* __restrict__ Wt,
            float* __restrict__ out,
            const int* __restrict__ offsets, const int* __restrict__ counts, int N, int K)
{
    int e = blockIdx.z;
    int cnt = counts[e];
    int m0 = blockIdx.y * 128;
    if (m0 >= cnt) return;
    int off = offsets[e];
    int n0 = blockIdx.x * 128;
    mma_core<false>(Ab + ((size_t)off + m0) * K, K, cnt - m0,
                    Wt + (size_t)e * K * N + (size_t)n0 * K, K, (const float*)0,
                    out + ((size_t)off + m0) * N + n0, N, K);
}

// ---------------- transpose kernels (round to tf32 on store) -------------------
// src [R,C] rows stride srcRS; dst [C,R] rows stride dstRS; batch via grid.z
__global__ void transpose_kernel(const float* __restrict__ src, float* __restrict__ dst,
                                 int srcRS, int dstRS, size_t srcBatch, size_t dstBatch)
{
    __shared__ float t[32][33];
    int z = blockIdx.z;
    src += (size_t)z * srcBatch;
    dst += (size_t)z * dstBatch;
    int c0 = blockIdx.x * 32, r0 = blockIdx.y * 32;
    int tx = threadIdx.x & 31, ty = threadIdx.x >> 5;
    #pragma unroll
    for (int i = 0; i < 4; i++)
        t[ty + i*8][tx] = src[(size_t)(r0 + ty + i*8) * srcRS + c0 + tx];
    __syncthreads();
    #pragma unroll
    for (int i = 0; i < 4; i++)
        dst[(size_t)(c0 + ty + i*8) * dstRS + r0 + tx] = to_tf32(t[tx][ty + i*8]);
}

__global__ void v_transpose_kernel(const float* __restrict__ v, float* __restrict__ vt)
{
    __shared__ float t[32][33];
    int z = blockIdx.z;                 // b*NKV + hk
    int b = z >> 2, hk = z & 3;
    const float* src = v + (size_t)b * SS * KVD + (size_t)hk * HD;   // [s][d], stride KVD
    float* dst = vt + (size_t)z * HD * SS;                           // [d][s], stride SS
    int c0 = blockIdx.x * 32, r0 = blockIdx.y * 32;  // c:d, r:s
    int tx = threadIdx.x & 31, ty = threadIdx.x >> 5;
    #pragma unroll
    for (int i = 0; i < 4; i++)
        t[ty + i*8][tx] = src[(size_t)(r0 + ty + i*8) * KVD + c0 + tx];
    __syncthreads();
    #pragma unroll
    for (int i = 0; i < 4; i++)
        dst[(size_t)(c0 + ty + i*8) * SS + r0 + tx] = to_tf32(t[tx][ty + i*8]);
}

// ---------------- small kernels ------------------------------------------------
__global__ void zero_counts_kernel(int* counts) {
    if (threadIdx.x < NE) counts[threadIdx.x] = 0;
}

__global__ void rmsnorm_kernel(const float* __restrict__ in, const float* __restrict__ w,
                               float* __restrict__ out) {
    int t = blockIdx.x;
    const float* row = in + (size_t)t * HH;
    float ss = 0.f;
    for (int h = threadIdx.x; h < HH; h += 256) { float v = row[h]; ss += v * v; }
    __shared__ float red[256];
    red[threadIdx.x] = ss; __syncthreads();
    for (int s = 128; s > 0; s >>= 1) {
        if (threadIdx.x < s) red[threadIdx.x] += red[threadIdx.x + s];
        __syncthreads();
    }
    float scale = rsqrtf(red[0] / (float)HH + 1e-5f);
    for (int h = threadIdx.x; h < HH; h += 256)
        out[(size_t)t * HH + h] = to_tf32(row[h] * scale * w[h]);
}

__global__ void rope_kernel(float* __restrict__ q, int nheads, int total) {
    int idx = blockIdx.x * blockDim.x + threadIdx.x;
    if (idx >= total) return;
    int d = idx & 63;
    int rest = idx >> 6;
    int head = rest % nheads;
    int t = rest / nheads;
    int s = t & (SS - 1);
    float inv = __powf(10000.f, -(float)d / 64.f);
    float ang = (float)s * inv;
    float c, si; __sincosf(ang, &si, &c);
    size_t base = (size_t)t * nheads * HD + (size_t)head * HD + d;
    float x1 = q[base], x2 = q[base + 64];
    q[base]      = to_tf32(x1 * c - x2 * si);
    q[base + 64] = to_tf32(x2 * c + x1 * si);
}

__global__ void softmax_kernel(float* __restrict__ scores) {
    int z = blockIdx.y, m = blockIdx.x;
    float* row = scores + (size_t)z * SS * SS + (size_t)m * SS;
    int n = m + 1;
    const float scale = 0.08838834764831845f; // 1/sqrt(128)
    __shared__ float red[256];
    float mx = -3.4e38f;
    for (int j = threadIdx.x; j < n; j += 256) mx = fmaxf(mx, row[j]);
    red[threadIdx.x] = mx; __syncthreads();
    for (int s = 128; s > 0; s >>= 1) {
        if (threadIdx.x < s) red[threadIdx.x] = fmaxf(red[threadIdx.x], red[threadIdx.x + s]);
        __syncthreads();
    }
    mx = red[0]; __syncthreads();
    float sum = 0.f;
    for (int j = threadIdx.x; j < n; j += 256) {
        float p = expf((row[j] - mx) * scale);
        row[j] = p;
        sum += p;
    }
    red[threadIdx.x] = sum; __syncthreads();
    for (int s = 128; s > 0; s >>= 1) {
        if (threadIdx.x < s) red[threadIdx.x] += red[threadIdx.x + s];
        __syncthreads();
    }
    float inv = 1.f / red[0];
    for (int j = threadIdx.x; j < n; j += 256) row[j] = to_tf32(row[j] * inv);
    int bound = ((m >> 7) + 1) << 7;
    for (int j = n + threadIdx.x; j < bound; j += 256) row[j] = 0.f;
}

__global__ void router_kernel(const float* __restrict__ x, const float* __restrict__ rw,
                              int* __restrict__ topi, float* __restrict__ topw,
                              int* __restrict__ counts)
{
    int t = blockIdx.x;
    const float* row = x + (size_t)t * HH;
    float acc[NE] = {};
    for (int h = threadIdx.x; h < HH; h += 256) {
        float v = row[h];
        const float* r = rw + (size_t)h * NE;
        #pragma unroll
        for (int e = 0; e < NE; e++) acc[e] += v * r[e];
    }
    __shared__ float red[256];
    __shared__ float logits[NE];
    for (int e = 0; e < NE; e++) {
        red[threadIdx.x] = acc[e]; __syncthreads();
        for (int s = 128; s > 0; s >>= 1) {
            if (threadIdx.x < s) red[threadIdx.x] += red[threadIdx.x + s];
            __syncthreads();
        }
        if (threadIdx.x == 0) logits[e] = red[0];
        __syncthreads();
    }
    if (threadIdx.x == 0) {
        float mx = logits[0];
        for (int e = 1; e < NE; e++) mx = fmaxf(mx, logits[e]);
        float p[NE];
        for (int e = 0; e < NE; e++) p[e] = expf(logits[e] - mx);
        int i1 = 0;
        for (int e = 1; e < NE; e++) if (p[e] > p[i1]) i1 = e;
        int i2 = (i1 == 0) ? 1 : 0;
        for (int e = 0; e < NE; e++) if (e != i1 && p[e] > p[i2]) i2 = e;
        float w1 = p[i1], w2 = p[i2];
        float inv = 1.f / (w1 + w2);
        topi[t * 2] = i1;  topi[t * 2 + 1] = i2;
        topw[t * 2] = w1 * inv;  topw[t * 2 + 1] = w2 * inv;
        atomicAdd(&counts[i1], 1);
        atomicAdd(&counts[i2], 1);
    }
}

__global__ void scan_kernel(const int* __restrict__ counts, int* __restrict__ offsets,
                            int* __restrict__ cursor) {
    if (threadIdx.x == 0) {
        int o = 0;
        for (int e = 0; e < NE; e++) { offsets[e] = o; cursor[e] = o; o += counts[e]; }
    }
}

__global__ void scatter_kernel(const int* __restrict__ topi, int* __restrict__ cursor,
                               int* __restrict__ tok, int* __restrict__ slot) {
    int t = blockIdx.x * blockDim.x + threadIdx.x;
    if (t >= TT) return;
    for (int j = 0; j < 2; j++) {
        int e = topi[t * 2 + j];
        int s = atomicAdd(&cursor[e], 1);
        tok[s] = t;
        slot[t * 2 + j] = s;
    }
}

__global__ void gather_kernel(const float* __restrict__ x, const int* __restrict__ tok,
                              float* __restrict__ xg) {
    size_t idx = (size_t)blockIdx.x * blockDim.x + threadIdx.x;
    int slot = (int)(idx >> 11);
    int h = (int)(idx & (HH - 1));
    xg[idx] = x[(size_t)tok[slot] * HH + h];
}

__global__ void silu_mul_kernel(const float* __restrict__ g, const float* __restrict__ u,
                                float* __restrict__ act) {
    size_t idx = (size_t)blockIdx.x * blockDim.x + threadIdx.x;
    float gv = g[idx], uv = u[idx];
    act[idx] = to_tf32(gv / (1.f + expf(-gv)) * uv);
}

__global__ void combine_kernel(const float* __restrict__ hid2, const float* __restrict__ y,
                               const int* __restrict__ slot, const float* __restrict__ topw,
                               float* __restrict__ out)
{
    size_t idx = (size_t)blockIdx.x * blockDim.x + threadIdx.x;
    int t = (int)(idx >> 11);
    int h = (int)(idx & (HH - 1));
    int s0 = slot[t * 2], s1 = slot[t * 2 + 1];
    float w0 = topw[t * 2], w1 = topw[t * 2 + 1];
    out[idx] = hid2[idx] + w0 * y[(size_t)s0 * HH + h] + w1 * y[(size_t)s1 * HH + h];
}

// ---------------- launch -------------------------------------------------------
extern "C" void kernel_launch(void* const* d_in, const int* in_sizes, int n_in,
                              void* d_out, int out_size)
{
    const float* hs  = (const float*)d_in[0];
    const float* ln1 = (const float*)d_in[1];
    const float* ln2 = (const float*)d_in[2];
    const float* wq  = (const float*)d_in[3];
    const float* wk  = (const float*)d_in[4];
    const float* wv  = (const float*)d_in[5];
    const float* wo  = (const float*)d_in[6];
    const float* rw  = (const float*)d_in[7];
    const float* gw  = (const float*)d_in[8];
    const float* uw  = (const float*)d_in[9];
    const float* dw  = (const float*)d_in[10];
    float* out = (float*)d_out;

    float *px, *pq, *pk, *pv, *pscores, *pattn, *phid2, *pxg, *pg, *pu, *py, *ptopw;
    float *pwqT, *pwkT, *pwvT, *pwoT, *pgwT, *puwT, *pdwT, *pvT;
    int *ptopi, *pcounts, *poffsets, *pcursor, *ptok, *pslot;
    cudaGetSymbolAddress((void**)&px, g_x);
    cudaGetSymbolAddress((void**)&pq, g_q);
    cudaGetSymbolAddress((void**)&pk, g_k);
    cudaGetSymbolAddress((void**)&pv, g_v);
    cudaGetSymbolAddress((void**)&pscores, g_scores);
    cudaGetSymbolAddress((void**)&pattn, g_attn);
    cudaGetSymbolAddress((void**)&phid2, g_hid2);
    cudaGetSymbolAddress((void**)&pxg, g_xg);
    cudaGetSymbolAddress((void**)&pg, g_g);
    cudaGetSymbolAddress((void**)&pu, g_u);
    cudaGetSymbolAddress((void**)&py, g_y);
    cudaGetSymbolAddress((void**)&ptopi, g_topi);
    cudaGetSymbolAddress((void**)&ptopw, g_topw);
    cudaGetSymbolAddress((void**)&pcounts, g_counts);
    cudaGetSymbolAddress((void**)&poffsets, g_offsets);
    cudaGetSymbolAddress((void**)&pcursor, g_cursor);
    cudaGetSymbolAddress((void**)&ptok, g_tok);
    cudaGetSymbolAddress((void**)&pslot, g_slot);
    cudaGetSymbolAddress((void**)&pwqT, g_wqT);
    cudaGetSymbolAddress((void**)&pwkT, g_wkT);
    cudaGetSymbolAddress((void**)&pwvT, g_wvT);
    cudaGetSymbolAddress((void**)&pwoT, g_woT);
    cudaGetSymbolAddress((void**)&pgwT, g_gwT);
    cudaGetSymbolAddress((void**)&puwT, g_uwT);
    cudaGetSymbolAddress((void**)&pdwT, g_dwT);
    cudaGetSymbolAddress((void**)&pvT, g_vT);

    cudaFuncSetAttribute(tc_gemm,   cudaFuncAttributeMaxDynamicSharedMemorySize, TC_SMEM_BYTES);
    cudaFuncSetAttribute(tc_scores, cudaFuncAttributeMaxDynamicSharedMemorySize, TC_SMEM_BYTES);
    cudaFuncSetAttribute(tc_pv,     cudaFuncAttributeMaxDynamicSharedMemorySize, TC_SMEM_BYTES);
    cudaFuncSetAttribute(tc_moe,    cudaFuncAttributeMaxDynamicSharedMemorySize, TC_SMEM_BYTES);

    // weight transposes (+tf32 preround)
    transpose_kernel<<<dim3(QD/32, HH/32, 1), 256>>>(wq, pwqT, QD, HH, 0, 0);
    transpose_kernel<<<dim3(KVD/32, HH/32, 1), 256>>>(wk, pwkT, KVD, HH, 0, 0);
    transpose_kernel<<<dim3(KVD/32, HH/32, 1), 256>>>(wv, pwvT, KVD, HH, 0, 0);
    transpose_kernel<<<dim3(HH/32, QD/32, 1), 256>>>(wo, pwoT, HH, QD, 0, 0);
    transpose_kernel<<<dim3(II/32, HH/32, NE), 256>>>(gw, pgwT, II, HH, (size_t)HH*II, (size_t)II*HH);
    transpose_kernel<<<dim3(II/32, HH/32, NE), 256>>>(uw, puwT, II, HH, (size_t)HH*II, (size_t)II*HH);
    transpose_kernel<<<dim3(HH/32, II/32, NE), 256>>>(dw, pdwT, HH, II, (size_t)II*HH, (size_t)HH*II);

    zero_counts_kernel<<<1, 32>>>(pcounts);
    rmsnorm_kernel<<<TT, 256>>>(hs, ln1, px);

    tc_gemm<<<dim3(QD/128,  TT/128), 256, TC_SMEM_BYTES>>>(px, pwqT, nullptr, pq, TT, QD,  HH);
    tc_gemm<<<dim3(KVD/128, TT/128), 256, TC_SMEM_BYTES>>>(px, pwkT, nullptr, pk, TT, KVD, HH);
    tc_gemm<<<dim3(KVD/128, TT/128), 256, TC_SMEM_BYTES>>>(px, pwvT, nullptr, pv, TT, KVD, HH);

    rope_kernel<<<(TT*NH*64)/256, 256>>>(pq, NH, TT*NH*64);
    rope_kernel<<<(TT*NKV*64)/256, 256>>>(pk, NKV, TT*NKV*64);
    v_transpose_kernel<<<dim3(HD/32, SS/32, BB*NKV), 256>>>(pv, pvT);

    tc_scores<<<dim3(SS/128, SS/128, BB*NH), 256, TC_SMEM_BYTES>>>(pq, pk, pscores);
    softmax_kernel<<<dim3(SS, BB*NH), 256>>>(pscores);
    tc_pv<<<dim3(1, SS/128, BB*NH), 256, TC_SMEM_BYTES>>>(pscores, pvT, pattn);

    tc_gemm<<<dim3(HH/128, TT/128), 256, TC_SMEM_BYTES>>>(pattn, pwoT, hs, phid2, TT, HH, QD);

    rmsnorm_kernel<<<TT, 256>>>(phid2, ln2, px);
    router_kernel<<<TT, 256>>>(px, rw, ptopi, ptopw, pcounts);
    scan_kernel<<<1, 32>>>(pcounts, poffsets, pcursor);
    scatter_kernel<<<TT/256, 256>>>(ptopi, pcursor, ptok, pslot);
    gather_kernel<<<(int)(((size_t)NSLOTS*HH)/256), 256>>>(px, ptok, pxg);

    tc_moe<<<dim3(II/128, NSLOTS/128, NE), 256, TC_SMEM_BYTES>>>(pxg, pgwT, pg, poffsets, pcounts, II, HH);
    tc_moe<<<dim3(II/128, NSLOTS/128, NE), 256, TC_SMEM_BYTES>>>(pxg, puwT, pu, poffsets, pcounts, II, HH);
    silu_mul_kernel<<<(int)(((size_t)NSLOTS*II)/256), 256>>>(pg, pu, pg);
    tc_moe<<<dim3(HH/128, NSLOTS/128, NE), 256, TC_SMEM_BYTES>>>(pg, pdwT, py, poffsets, pcounts, HH, II);

    combine_kernel<<<(int)(((size_t)TT*HH)/256), 256>>>(phid2, py, pslot, ptopw, out);
}